// round 1
// baseline (speedup 1.0000x reference)
#include <cuda_runtime.h>
#include <cuda_bf16.h>
#include <math.h>

// Problem constants
#define L 512
#define Dm 1024
#define NH 16
#define NKV 4
#define NR 16
#define HD 64
#define ATTN_SCALE 0.125f
#define REL_SCALE 0.125f

// ---------------- scratch (__device__ globals; no allocations allowed) -------
__device__ float g_Q[L * NH * HD];      // 512x1024
__device__ float g_K[L * NKV * HD];     // 512x256
__device__ float g_QR[L * NR * HD];     // 512x1024
__device__ float g_KR[L * NR * HD];     // 512x1024
__device__ float g_SV[L * NKV * HD];    // 512x256
__device__ float g_S[L * NH * NR];      // 512x16x16
__device__ float g_CTX[L * NH * HD];    // 512x1024

// ---------------- generic tiled SGEMM: C = alpha * A(MxK) @ B(KxN) ----------
// M,N multiples of 64; K multiple of 16. 256 threads, 64x64 tile, 4x4 micro.
__global__ void sgemm_kernel(const float* __restrict__ A, const float* __restrict__ B,
                             float* __restrict__ C, int M, int N, int K, float alpha) {
    __shared__ float As[16][64 + 1];
    __shared__ float Bs[16][64];
    int bx = blockIdx.x, by = blockIdx.y;
    int tid = threadIdx.x;
    int trow = (tid >> 4) << 2;
    int tcol = (tid & 15) << 2;
    int rowA = by * 64, colB = bx * 64;
    float acc[4][4] = {};
    for (int k0 = 0; k0 < K; k0 += 16) {
        #pragma unroll
        for (int t = tid; t < 64 * 16; t += 256) {
            int m = t >> 4, kk = t & 15;
            As[kk][m] = A[(size_t)(rowA + m) * K + k0 + kk];
        }
        #pragma unroll
        for (int t = tid; t < 16 * 64; t += 256) {
            int kk = t >> 6, n = t & 63;
            Bs[kk][n] = B[(size_t)(k0 + kk) * N + colB + n];
        }
        __syncthreads();
        #pragma unroll
        for (int kk = 0; kk < 16; kk++) {
            float a[4], b[4];
            #pragma unroll
            for (int u = 0; u < 4; u++) a[u] = As[kk][trow + u];
            #pragma unroll
            for (int v = 0; v < 4; v++) b[v] = Bs[kk][tcol + v];
            #pragma unroll
            for (int u = 0; u < 4; u++)
                #pragma unroll
                for (int v = 0; v < 4; v++) acc[u][v] += a[u] * b[v];
        }
        __syncthreads();
    }
    #pragma unroll
    for (int u = 0; u < 4; u++)
        #pragma unroll
        for (int v = 0; v < 4; v++)
            C[(size_t)(rowA + trow + u) * N + colB + tcol + v] = alpha * acc[u][v];
}

// ---------------- RoPE (in place). nheads = 16 for Q, 4 for K ---------------
__global__ void rope_kernel(float* __restrict__ t, const float* __restrict__ pcos,
                            const float* __restrict__ psin, int nheads) {
    int idx = blockIdx.x * blockDim.x + threadIdx.x;
    int total = L * nheads * (HD / 2);
    if (idx >= total) return;
    int p = idx & 31;
    int rest = idx >> 5;
    int hh = rest % nheads;
    int i = rest / nheads;
    float c = pcos[i * 32 + p], s = psin[i * 32 + p];
    float* base = t + ((size_t)i * nheads + hh) * HD + 2 * p;
    float re = base[0], im = base[1];
    base[0] = re * c - im * s;
    base[1] = re * s + im * c;
}

// ---------------- scores: attn_raw[h,i,j] = scale * q_h[i].k_{h/4}[j] -------
// Causal: skip tiles fully above diagonal. grid (jt, it, h), 64x64 tiles.
__global__ void scores_kernel(const float* __restrict__ Q, const float* __restrict__ K,
                              float* __restrict__ attn) {
    int h = blockIdx.z;
    int by = blockIdx.y, bx = blockIdx.x;
    if (bx > by) return;
    __shared__ float Qs[64][65];
    __shared__ float Ks[64][65];
    int tid = threadIdx.x;
    int i0 = by * 64, j0 = bx * 64;
    const float* Qh = Q + h * HD;
    const float* Kh = K + (h >> 2) * HD;
    #pragma unroll
    for (int t = tid; t < 64 * 64; t += 256) {
        int r = t >> 6, c = t & 63;
        Qs[r][c] = Qh[(size_t)(i0 + r) * (NH * HD) + c];
        Ks[r][c] = Kh[(size_t)(j0 + r) * (NKV * HD) + c];
    }
    __syncthreads();
    int trow = (tid >> 4) << 2;
    int tcol = (tid & 15) << 2;
    float acc[4][4] = {};
    #pragma unroll
    for (int d = 0; d < 64; d++) {
        float a[4], b[4];
        #pragma unroll
        for (int u = 0; u < 4; u++) { a[u] = Qs[trow + u][d]; b[u] = Ks[tcol + u][d]; }
        #pragma unroll
        for (int u = 0; u < 4; u++)
            #pragma unroll
            for (int v = 0; v < 4; v++) acc[u][v] += a[u] * b[v];
    }
    #pragma unroll
    for (int u = 0; u < 4; u++)
        #pragma unroll
        for (int v = 0; v < 4; v++)
            attn[((size_t)h * L + i0 + trow + u) * L + j0 + tcol + v] = acc[u][v] * ATTN_SCALE;
}

// ---------------- causal softmax in place over attn rows --------------------
__global__ void softmax_kernel(float* __restrict__ attn) {
    int row = blockIdx.x;            // h*L + i
    int i = row & (L - 1);
    float* p = attn + (size_t)row * L;
    int len = i + 1;
    int tid = threadIdx.x;           // 256
    __shared__ float rowv[L];
    __shared__ float red[256];
    for (int j = tid; j < L; j += 256) rowv[j] = (j < len) ? p[j] : -3.0e38f;
    __syncthreads();
    float m = -3.0e38f;
    for (int j = tid; j < L; j += 256) m = fmaxf(m, rowv[j]);
    red[tid] = m; __syncthreads();
    for (int s = 128; s > 0; s >>= 1) { if (tid < s) red[tid] = fmaxf(red[tid], red[tid + s]); __syncthreads(); }
    m = red[0]; __syncthreads();
    float sum = 0.f;
    for (int j = tid; j < L; j += 256) {
        float e = (j < len) ? __expf(rowv[j] - m) : 0.f;
        rowv[j] = e;
        sum += e;
    }
    red[tid] = sum; __syncthreads();
    for (int s = 128; s > 0; s >>= 1) { if (tid < s) red[tid] += red[tid + s]; __syncthreads(); }
    float inv = 1.f / red[0];
    for (int j = tid; j < L; j += 256) p[j] = (j < len) ? rowv[j] * inv : 0.f;
}

// ---------------- relations[i,j,r] = REL_SCALE * qr[i,r].kr[j,r] (full) -----
__global__ void relations_kernel(const float* __restrict__ QR, const float* __restrict__ KR,
                                 float* __restrict__ rel) {
    int r = blockIdx.z;
    int by = blockIdx.y, bx = blockIdx.x;
    __shared__ float Qs[64][65];
    __shared__ float Ks[64][65];
    int tid = threadIdx.x;
    int i0 = by * 64, j0 = bx * 64;
    const float* Qh = QR + r * HD;
    const float* Kh = KR + r * HD;
    #pragma unroll
    for (int t = tid; t < 64 * 64; t += 256) {
        int rr = t >> 6, c = t & 63;
        Qs[rr][c] = Qh[(size_t)(i0 + rr) * (NR * HD) + c];
        Ks[rr][c] = Kh[(size_t)(j0 + rr) * (NR * HD) + c];
    }
    __syncthreads();
    int trow = (tid >> 4) << 2;
    int tcol = (tid & 15) << 2;
    float acc[4][4] = {};
    #pragma unroll
    for (int d = 0; d < 64; d++) {
        float a[4], b[4];
        #pragma unroll
        for (int u = 0; u < 4; u++) { a[u] = Qs[trow + u][d]; b[u] = Ks[tcol + u][d]; }
        #pragma unroll
        for (int u = 0; u < 4; u++)
            #pragma unroll
            for (int v = 0; v < 4; v++) acc[u][v] += a[u] * b[v];
    }
    #pragma unroll
    for (int u = 0; u < 4; u++)
        #pragma unroll
        for (int v = 0; v < 4; v++)
            rel[((size_t)(i0 + trow + u) * L + j0 + tcol + v) * NR + r] = acc[u][v] * REL_SCALE;
}

// ---------------- S[i,h,r] = sum_j attn[h,i,j] * rel[i,j,r] -----------------
__global__ void s_kernel(const float* __restrict__ attn, const float* __restrict__ rel,
                         float* __restrict__ S) {
    int i = blockIdx.x;
    int tid = threadIdx.x;           // 256 = 16 h * 16 r
    int h = tid >> 4, r = tid & 15;
    __shared__ float attnS[16][128];
    float acc = 0.f;
    int len = i + 1;                  // attn rows are zero beyond i
    for (int j0 = 0; j0 < len; j0 += 128) {
        int n = min(128, len - j0);
        for (int t = tid; t < 16 * 128; t += 256) {
            int hh = t >> 7, jj = t & 127;
            attnS[hh][jj] = (jj < n) ? attn[((size_t)hh * L + i) * L + j0 + jj] : 0.f;
        }
        __syncthreads();
        for (int jj = 0; jj < n; jj++)
            acc += attnS[h][jj] * rel[((size_t)i * L + j0 + jj) * NR + r];
        __syncthreads();
    }
    S[((size_t)i * NH + h) * NR + r] = acc;
}

// ---- ctx[i, h*64+d] = sum_j attn[h,i,j]*sv[j,h/4,d] + sum_r S[i,h,r]*wr[r,h*64+d]
__global__ void attended_kernel(const float* __restrict__ attn, const float* __restrict__ SV,
                                const float* __restrict__ S, const float* __restrict__ wr,
                                float* __restrict__ ctx) {
    int h = blockIdx.y;
    int by = blockIdx.x;
    int i0 = by * 64;
    __shared__ float As[16][64 + 1];  // [k][m]
    __shared__ float Bs[16][64];
    int tid = threadIdx.x;
    int trow = (tid >> 4) << 2;
    int tcol = (tid & 15) << 2;
    float acc[4][4] = {};
    const float* Ah = attn + (size_t)h * L * L;
    const float* Bh = SV + (h >> 2) * HD;
    int jmax = i0 + 64;               // causal: attn zero beyond row index
    for (int k0 = 0; k0 < jmax; k0 += 16) {
        #pragma unroll
        for (int t = tid; t < 64 * 16; t += 256) {
            int m = t >> 4, kk = t & 15;
            As[kk][m] = Ah[(size_t)(i0 + m) * L + k0 + kk];
        }
        #pragma unroll
        for (int t = tid; t < 16 * 64; t += 256) {
            int kk = t >> 6, n = t & 63;
            Bs[kk][n] = Bh[(size_t)(k0 + kk) * (NKV * HD) + n];
        }
        __syncthreads();
        #pragma unroll
        for (int kk = 0; kk < 16; kk++) {
            float a[4], b[4];
            #pragma unroll
            for (int u = 0; u < 4; u++) { a[u] = As[kk][trow + u]; b[u] = Bs[kk][tcol + u]; }
            #pragma unroll
            for (int u = 0; u < 4; u++)
                #pragma unroll
                for (int v = 0; v < 4; v++) acc[u][v] += a[u] * b[v];
        }
        __syncthreads();
    }
    // epilogue: += S(64x16) @ wr_h(16x64)
    __shared__ float wrs[16][64];
    __shared__ float Ss[64][17];
    for (int t = tid; t < 16 * 64; t += 256) {
        int rr = t >> 6, n = t & 63;
        wrs[rr][n] = wr[(size_t)rr * (NH * HD) + h * HD + n];
    }
    for (int t = tid; t < 64 * 16; t += 256) {
        int m = t >> 4, rr = t & 15;
        Ss[m][rr] = S[((size_t)(i0 + m) * NH + h) * NR + rr];
    }
    __syncthreads();
    #pragma unroll
    for (int rr = 0; rr < 16; rr++) {
        float a[4], b[4];
        #pragma unroll
        for (int u = 0; u < 4; u++) { a[u] = Ss[trow + u][rr]; b[u] = wrs[rr][tcol + u]; }
        #pragma unroll
        for (int u = 0; u < 4; u++)
            #pragma unroll
            for (int v = 0; v < 4; v++) acc[u][v] += a[u] * b[v];
    }
    #pragma unroll
    for (int u = 0; u < 4; u++)
        #pragma unroll
        for (int v = 0; v < 4; v++)
            ctx[(size_t)(i0 + trow + u) * (NH * HD) + h * HD + tcol + v] = acc[u][v];
}

// ---------------------------------------------------------------------------
extern "C" void kernel_launch(void* const* d_in, const int* in_sizes, int n_in,
                              void* d_out, int out_size) {
    const float* x       = (const float*)d_in[0];
    const float* symbols = (const float*)d_in[1];
    const float* fcos    = (const float*)d_in[2];
    const float* fsin    = (const float*)d_in[3];
    const float* wq_attn = (const float*)d_in[4];
    const float* wk_attn = (const float*)d_in[5];
    const float* wq_rel  = (const float*)d_in[6];
    const float* wk_rel  = (const float*)d_in[7];
    const float* wr      = (const float*)d_in[8];
    const float* wv      = (const float*)d_in[9];
    const float* wo      = (const float*)d_in[10];

    float* out  = (float*)d_out;                    // 512*1024
    float* attn = out + (size_t)L * NH * HD;        // 16*512*512
    float* rel  = attn + (size_t)NH * L * L;        // 512*512*16

    float *Q, *K, *QR, *KR, *SV, *S, *CTX;
    cudaGetSymbolAddress((void**)&Q,  g_Q);
    cudaGetSymbolAddress((void**)&K,  g_K);
    cudaGetSymbolAddress((void**)&QR, g_QR);
    cudaGetSymbolAddress((void**)&KR, g_KR);
    cudaGetSymbolAddress((void**)&SV, g_SV);
    cudaGetSymbolAddress((void**)&S,  g_S);
    cudaGetSymbolAddress((void**)&CTX, g_CTX);

    // 1) projections
    sgemm_kernel<<<dim3(16, 8), 256>>>(x, wq_attn, Q, L, NH * HD, Dm, 1.f);
    sgemm_kernel<<<dim3(4, 8), 256>>>(x, wk_attn, K, L, NKV * HD, Dm, 1.f);
    sgemm_kernel<<<dim3(16, 8), 256>>>(x, wq_rel, QR, L, NR * HD, Dm, 1.f);
    sgemm_kernel<<<dim3(16, 8), 256>>>(x, wk_rel, KR, L, NR * HD, Dm, 1.f);
    sgemm_kernel<<<dim3(4, 8), 256>>>(symbols, wv, SV, L, NKV * HD, Dm, 1.f);

    // 2) RoPE on Q, K
    rope_kernel<<<(L * NH * 32 + 255) / 256, 256>>>(Q, fcos, fsin, NH);
    rope_kernel<<<(L * NKV * 32 + 255) / 256, 256>>>(K, fcos, fsin, NKV);

    // 3) scores (causal tiles) + softmax -> attn output region
    scores_kernel<<<dim3(8, 8, NH), 256>>>(Q, K, attn);
    softmax_kernel<<<NH * L, 256>>>(attn);

    // 4) relations -> relations output region
    relations_kernel<<<dim3(8, 8, NR), 256>>>(QR, KR, rel);

    // 5) S[i,h,r] = sum_j attn * rel   (factorized attended_relations)
    s_kernel<<<L, 256>>>(attn, rel, S);

    // 6) ctx = attn@sv + S@wr
    attended_kernel<<<dim3(8, NH), 256>>>(attn, SV, S, wr, CTX);

    // 7) out = ctx @ wo
    sgemm_kernel<<<dim3(16, 8), 256>>>(CTX, wo, out, L, NH * HD, Dm, 1.f);
}

// round 3
// speedup vs baseline: 3.0365x; 3.0365x over previous
#include <cuda_runtime.h>
#include <cuda_bf16.h>
#include <cstdint>
#include <math.h>

#define L 512
#define Dm 1024
#define NH 16
#define NKV 4
#define NR 16
#define HD 64
#define ATTN_SCALE 0.125f
#define REL_SCALE 0.125f

// ---------------- scratch (__device__ globals; no allocations allowed) ------
__device__ float g_Q[L * NH * HD];
__device__ float g_K[L * NKV * HD];
__device__ float g_QR[L * NR * HD];
__device__ float g_KR[L * NR * HD];
__device__ float g_SV[L * NKV * HD];
__device__ float g_S[L * NH * NR];
__device__ float g_CTX[L * NH * HD];
// transposed weights: wq(1M) wqr(1M) wkr(1M) wo(1M) wk(256K) wv(256K)
__device__ float g_WT[4 * 1024 * 1024 + 2 * 1024 * 256];

__device__ __forceinline__ float to_tf32(float x) {
    uint32_t u;
    asm("cvt.rna.tf32.f32 %0, %1;" : "=r"(u) : "f"(x));
    return __uint_as_float(u);
}

// ---------------- tf32 mma.sync GEMM ----------------------------------------
// C[128,64] tile = A[M,K] @ Wt^T, Wt stored [N,K] row-major.
// 256 threads = 8 warps as 4(m) x 2(n); warp tile 32x32 = 2x4 m16n8k8 atoms.
__device__ __forceinline__ void mma_gemm_tile(
    const float* __restrict__ A, int lda,
    const float* __restrict__ Wt,
    float* __restrict__ C, int ldc,
    int m0, int n0, int K)
{
    __shared__ float As[128][36];   // [m][k], pad 36 -> 16B-aligned rows, no LDS conflicts
    __shared__ float Bs[64][36];    // [n][k]

    int tid = threadIdx.x;
    int warp = tid >> 5;
    int lane = tid & 31;
    int tq = lane >> 2;             // 0..7
    int tr = lane & 3;              // 0..3
    int wm = warp & 3;              // m-warp 0..3
    int wn = warp >> 2;             // n-warp 0..1
    int mb = wm * 32;
    int nb = wn * 32;

    float c[2][4][4];
    #pragma unroll
    for (int i = 0; i < 2; i++)
        #pragma unroll
        for (int j = 0; j < 4; j++)
            #pragma unroll
            for (int k = 0; k < 4; k++) c[i][j][k] = 0.f;

    for (int k0 = 0; k0 < K; k0 += 32) {
        // stage A chunk: 128 rows x 32 cols; 1024 float4 over 256 thr = 4 each
        #pragma unroll
        for (int i = 0; i < 4; i++) {
            int e = tid + i * 256;
            int r = e >> 3, c4 = e & 7;
            float4 v = *reinterpret_cast<const float4*>(&A[(size_t)(m0 + r) * lda + k0 + c4 * 4]);
            v.x = to_tf32(v.x); v.y = to_tf32(v.y); v.z = to_tf32(v.z); v.w = to_tf32(v.w);
            *reinterpret_cast<float4*>(&As[r][c4 * 4]) = v;
        }
        // stage B chunk: 64 rows x 32 cols; 512 float4 = 2 each
        #pragma unroll
        for (int i = 0; i < 2; i++) {
            int e = tid + i * 256;
            int r = e >> 3, c4 = e & 7;
            float4 v = *reinterpret_cast<const float4*>(&Wt[(size_t)(n0 + r) * K + k0 + c4 * 4]);
            v.x = to_tf32(v.x); v.y = to_tf32(v.y); v.z = to_tf32(v.z); v.w = to_tf32(v.w);
            *reinterpret_cast<float4*>(&Bs[r][c4 * 4]) = v;
        }
        __syncthreads();
        #pragma unroll
        for (int ks = 0; ks < 4; ks++) {
            int kb = ks * 8;
            uint32_t a[2][4], b[4][2];
            #pragma unroll
            for (int ma = 0; ma < 2; ma++) {
                int r0 = mb + ma * 16 + tq;
                a[ma][0] = __float_as_uint(As[r0][kb + tr]);
                a[ma][1] = __float_as_uint(As[r0 + 8][kb + tr]);
                a[ma][2] = __float_as_uint(As[r0][kb + tr + 4]);
                a[ma][3] = __float_as_uint(As[r0 + 8][kb + tr + 4]);
            }
            #pragma unroll
            for (int na = 0; na < 4; na++) {
                int n_ = nb + na * 8 + tq;
                b[na][0] = __float_as_uint(Bs[n_][kb + tr]);
                b[na][1] = __float_as_uint(Bs[n_][kb + tr + 4]);
            }
            #pragma unroll
            for (int ma = 0; ma < 2; ma++)
                #pragma unroll
                for (int na = 0; na < 4; na++) {
                    asm volatile(
                        "mma.sync.aligned.m16n8k8.row.col.f32.tf32.tf32.f32 "
                        "{%0,%1,%2,%3}, {%4,%5,%6,%7}, {%8,%9}, {%0,%1,%2,%3};"
                        : "+f"(c[ma][na][0]), "+f"(c[ma][na][1]),
                          "+f"(c[ma][na][2]), "+f"(c[ma][na][3])
                        : "r"(a[ma][0]), "r"(a[ma][1]), "r"(a[ma][2]), "r"(a[ma][3]),
                          "r"(b[na][0]), "r"(b[na][1]));
                }
        }
        __syncthreads();
    }

    // epilogue: c0,c1 at (row, col..col+1), c2,c3 at (row+8, ...)
    #pragma unroll
    for (int ma = 0; ma < 2; ma++) {
        int row = m0 + mb + ma * 16 + tq;
        #pragma unroll
        for (int na = 0; na < 4; na++) {
            int col = n0 + nb + na * 8 + 2 * tr;
            *reinterpret_cast<float2*>(&C[(size_t)row * ldc + col]) =
                make_float2(c[ma][na][0], c[ma][na][1]);
            *reinterpret_cast<float2*>(&C[(size_t)(row + 8) * ldc + col]) =
                make_float2(c[ma][na][2], c[ma][na][3]);
        }
    }
}

// fused projections: grid (4 mtiles, 56 ntiles)
__global__ void __launch_bounds__(256, 2) proj_mma_kernel(
    const float* __restrict__ x, const float* __restrict__ symbols,
    const float* __restrict__ wtq, const float* __restrict__ wtqr,
    const float* __restrict__ wtkr, const float* __restrict__ wtk,
    const float* __restrict__ wtv,
    float* __restrict__ Q, float* __restrict__ Kp, float* __restrict__ QR,
    float* __restrict__ KR, float* __restrict__ SV)
{
    int mt = blockIdx.x;
    int t = blockIdx.y;
    const float* A = x;
    const float* Wt;
    float* C;
    int ldc, n0;
    if (t < 16)      { Wt = wtq;  C = Q;  ldc = 1024; n0 = t * 64; }
    else if (t < 32) { Wt = wtqr; C = QR; ldc = 1024; n0 = (t - 16) * 64; }
    else if (t < 48) { Wt = wtkr; C = KR; ldc = 1024; n0 = (t - 32) * 64; }
    else if (t < 52) { Wt = wtk;  C = Kp; ldc = 256;  n0 = (t - 48) * 64; }
    else             { Wt = wtv; A = symbols; C = SV; ldc = 256; n0 = (t - 52) * 64; }
    mma_gemm_tile(A, 1024, Wt, C, ldc, mt * 128, n0, 1024);
}

__global__ void __launch_bounds__(256, 2) out_mma_kernel(
    const float* __restrict__ CTX, const float* __restrict__ wto, float* __restrict__ out)
{
    mma_gemm_tile(CTX, 1024, wto, out, 1024, blockIdx.x * 128, blockIdx.y * 64, 1024);
}

// ---------------- weight transpose ------------------------------------------
__global__ void transpose_kernel(const float* __restrict__ src, float* __restrict__ dst,
                                 int R, int C) {
    __shared__ float t[32][33];
    int bx = blockIdx.x * 32, by = blockIdx.y * 32;
    int x = threadIdx.x, y = threadIdx.y;   // 32 x 8
    for (int i = y; i < 32; i += 8)
        t[i][x] = src[(size_t)(by + i) * C + bx + x];
    __syncthreads();
    for (int i = y; i < 32; i += 8)
        dst[(size_t)(bx + i) * R + by + x] = t[x][i];
}

// ---------------- RoPE (in place) -------------------------------------------
__global__ void rope_kernel(float* __restrict__ t, const float* __restrict__ pcos,
                            const float* __restrict__ psin, int nheads) {
    int idx = blockIdx.x * blockDim.x + threadIdx.x;
    int total = L * nheads * (HD / 2);
    if (idx >= total) return;
    int p = idx & 31;
    int rest = idx >> 5;
    int hh = rest % nheads;
    int i = rest / nheads;
    float c = pcos[i * 32 + p], s = psin[i * 32 + p];
    float* base = t + ((size_t)i * nheads + hh) * HD + 2 * p;
    float re = base[0], im = base[1];
    base[0] = re * c - im * s;
    base[1] = re * s + im * c;
}

// ---------------- scores ----------------------------------------------------
__global__ void scores_kernel(const float* __restrict__ Q, const float* __restrict__ K,
                              float* __restrict__ attn) {
    int h = blockIdx.z;
    int by = blockIdx.y, bx = blockIdx.x;
    if (bx > by) return;
    __shared__ float Qs[64][65];
    __shared__ float Ks[64][65];
    int tid = threadIdx.x;
    int i0 = by * 64, j0 = bx * 64;
    const float* Qh = Q + h * HD;
    const float* Kh = K + (h >> 2) * HD;
    #pragma unroll
    for (int t = tid; t < 64 * 64; t += 256) {
        int r = t >> 6, c = t & 63;
        Qs[r][c] = Qh[(size_t)(i0 + r) * (NH * HD) + c];
        Ks[r][c] = Kh[(size_t)(j0 + r) * (NKV * HD) + c];
    }
    __syncthreads();
    int trow = (tid >> 4) << 2;
    int tcol = (tid & 15) << 2;
    float acc[4][4] = {};
    #pragma unroll
    for (int d = 0; d < 64; d++) {
        float a[4], b[4];
        #pragma unroll
        for (int u = 0; u < 4; u++) { a[u] = Qs[trow + u][d]; b[u] = Ks[tcol + u][d]; }
        #pragma unroll
        for (int u = 0; u < 4; u++)
            #pragma unroll
            for (int v = 0; v < 4; v++) acc[u][v] += a[u] * b[v];
    }
    #pragma unroll
    for (int u = 0; u < 4; u++)
        #pragma unroll
        for (int v = 0; v < 4; v++)
            attn[((size_t)h * L + i0 + trow + u) * L + j0 + tcol + v] = acc[u][v] * ATTN_SCALE;
}

// ---------------- causal softmax --------------------------------------------
__global__ void softmax_kernel(float* __restrict__ attn) {
    int row = blockIdx.x;
    int i = row & (L - 1);
    float* p = attn + (size_t)row * L;
    int len = i + 1;
    int tid = threadIdx.x;
    __shared__ float rowv[L];
    __shared__ float red[256];
    for (int j = tid; j < L; j += 256) rowv[j] = (j < len) ? p[j] : -3.0e38f;
    __syncthreads();
    float m = -3.0e38f;
    for (int j = tid; j < L; j += 256) m = fmaxf(m, rowv[j]);
    red[tid] = m; __syncthreads();
    for (int s = 128; s > 0; s >>= 1) { if (tid < s) red[tid] = fmaxf(red[tid], red[tid + s]); __syncthreads(); }
    m = red[0]; __syncthreads();
    float sum = 0.f;
    for (int j = tid; j < L; j += 256) {
        float e = (j < len) ? __expf(rowv[j] - m) : 0.f;
        rowv[j] = e;
        sum += e;
    }
    red[tid] = sum; __syncthreads();
    for (int s = 128; s > 0; s >>= 1) { if (tid < s) red[tid] += red[tid + s]; __syncthreads(); }
    float inv = 1.f / red[0];
    for (int j = tid; j < L; j += 256) p[j] = (j < len) ? rowv[j] * inv : 0.f;
}

// ---------------- relations -------------------------------------------------
__global__ void relations_kernel(const float* __restrict__ QR, const float* __restrict__ KR,
                                 float* __restrict__ rel) {
    int r = blockIdx.z;
    int by = blockIdx.y, bx = blockIdx.x;
    __shared__ float Qs[64][65];
    __shared__ float Ks[64][65];
    int tid = threadIdx.x;
    int i0 = by * 64, j0 = bx * 64;
    const float* Qh = QR + r * HD;
    const float* Kh = KR + r * HD;
    #pragma unroll
    for (int t = tid; t < 64 * 64; t += 256) {
        int rr = t >> 6, c = t & 63;
        Qs[rr][c] = Qh[(size_t)(i0 + rr) * (NR * HD) + c];
        Ks[rr][c] = Kh[(size_t)(j0 + rr) * (NR * HD) + c];
    }
    __syncthreads();
    int trow = (tid >> 4) << 2;
    int tcol = (tid & 15) << 2;
    float acc[4][4] = {};
    #pragma unroll
    for (int d = 0; d < 64; d++) {
        float a[4], b[4];
        #pragma unroll
        for (int u = 0; u < 4; u++) { a[u] = Qs[trow + u][d]; b[u] = Ks[tcol + u][d]; }
        #pragma unroll
        for (int u = 0; u < 4; u++)
            #pragma unroll
            for (int v = 0; v < 4; v++) acc[u][v] += a[u] * b[v];
    }
    #pragma unroll
    for (int u = 0; u < 4; u++)
        #pragma unroll
        for (int v = 0; v < 4; v++)
            rel[((size_t)(i0 + trow + u) * L + j0 + tcol + v) * NR + r] = acc[u][v] * REL_SCALE;
}

// ---------------- S[i,h,r] = sum_j attn[h,i,j] * rel[i,j,r] -----------------
__global__ void s_kernel(const float* __restrict__ attn, const float* __restrict__ rel,
                         float* __restrict__ S) {
    int i = blockIdx.x;
    int tid = threadIdx.x;
    int h = tid >> 4, r = tid & 15;
    __shared__ float attnS[16][128];
    float acc = 0.f;
    int len = i + 1;
    for (int j0 = 0; j0 < len; j0 += 128) {
        int n = min(128, len - j0);
        for (int t = tid; t < 16 * 128; t += 256) {
            int hh = t >> 7, jj = t & 127;
            attnS[hh][jj] = (jj < n) ? attn[((size_t)hh * L + i) * L + j0 + jj] : 0.f;
        }
        __syncthreads();
        for (int jj = 0; jj < n; jj++)
            acc += attnS[h][jj] * rel[((size_t)i * L + j0 + jj) * NR + r];
        __syncthreads();
    }
    S[((size_t)i * NH + h) * NR + r] = acc;
}

// ---- ctx = attn@sv + S@wr ---------------------------------------------------
__global__ void attended_kernel(const float* __restrict__ attn, const float* __restrict__ SV,
                                const float* __restrict__ S, const float* __restrict__ wr,
                                float* __restrict__ ctx) {
    int h = blockIdx.y;
    int by = blockIdx.x;
    int i0 = by * 64;
    __shared__ float As[16][64 + 1];
    __shared__ float Bs[16][64];
    int tid = threadIdx.x;
    int trow = (tid >> 4) << 2;
    int tcol = (tid & 15) << 2;
    float acc[4][4] = {};
    const float* Ah = attn + (size_t)h * L * L;
    const float* Bh = SV + (h >> 2) * HD;
    int jmax = i0 + 64;
    for (int k0 = 0; k0 < jmax; k0 += 16) {
        #pragma unroll
        for (int t = tid; t < 64 * 16; t += 256) {
            int m = t >> 4, kk = t & 15;
            As[kk][m] = Ah[(size_t)(i0 + m) * L + k0 + kk];
        }
        #pragma unroll
        for (int t = tid; t < 16 * 64; t += 256) {
            int kk = t >> 6, n = t & 63;
            Bs[kk][n] = Bh[(size_t)(k0 + kk) * (NKV * HD) + n];
        }
        __syncthreads();
        #pragma unroll
        for (int kk = 0; kk < 16; kk++) {
            float a[4], b[4];
            #pragma unroll
            for (int u = 0; u < 4; u++) { a[u] = As[kk][trow + u]; b[u] = Bs[kk][tcol + u]; }
            #pragma unroll
            for (int u = 0; u < 4; u++)
                #pragma unroll
                for (int v = 0; v < 4; v++) acc[u][v] += a[u] * b[v];
        }
        __syncthreads();
    }
    __shared__ float wrs[16][64];
    __shared__ float Ss[64][17];
    for (int t = tid; t < 16 * 64; t += 256) {
        int rr = t >> 6, n = t & 63;
        wrs[rr][n] = wr[(size_t)rr * (NH * HD) + h * HD + n];
    }
    for (int t = tid; t < 64 * 16; t += 256) {
        int m = t >> 4, rr = t & 15;
        Ss[m][rr] = S[((size_t)(i0 + m) * NH + h) * NR + rr];
    }
    __syncthreads();
    #pragma unroll
    for (int rr = 0; rr < 16; rr++) {
        float a[4], b[4];
        #pragma unroll
        for (int u = 0; u < 4; u++) { a[u] = Ss[trow + u][rr]; b[u] = wrs[rr][tcol + u]; }
        #pragma unroll
        for (int u = 0; u < 4; u++)
            #pragma unroll
            for (int v = 0; v < 4; v++) acc[u][v] += a[u] * b[v];
    }
    #pragma unroll
    for (int u = 0; u < 4; u++)
        #pragma unroll
        for (int v = 0; v < 4; v++)
            ctx[(size_t)(i0 + trow + u) * (NH * HD) + h * HD + tcol + v] = acc[u][v];
}

// ---------------------------------------------------------------------------
extern "C" void kernel_launch(void* const* d_in, const int* in_sizes, int n_in,
                              void* d_out, int out_size) {
    const float* x       = (const float*)d_in[0];
    const float* symbols = (const float*)d_in[1];
    const float* fcos    = (const float*)d_in[2];
    const float* fsin    = (const float*)d_in[3];
    const float* wq_attn = (const float*)d_in[4];
    const float* wk_attn = (const float*)d_in[5];
    const float* wq_rel  = (const float*)d_in[6];
    const float* wk_rel  = (const float*)d_in[7];
    const float* wr      = (const float*)d_in[8];
    const float* wv      = (const float*)d_in[9];
    const float* wo      = (const float*)d_in[10];

    float* out  = (float*)d_out;
    float* attn = out + (size_t)L * NH * HD;
    float* rel  = attn + (size_t)NH * L * L;

    float *Q, *K, *QR, *KR, *SV, *S, *CTX, *WT;
    cudaGetSymbolAddress((void**)&Q,  g_Q);
    cudaGetSymbolAddress((void**)&K,  g_K);
    cudaGetSymbolAddress((void**)&QR, g_QR);
    cudaGetSymbolAddress((void**)&KR, g_KR);
    cudaGetSymbolAddress((void**)&SV, g_SV);
    cudaGetSymbolAddress((void**)&S,  g_S);
    cudaGetSymbolAddress((void**)&CTX, g_CTX);
    cudaGetSymbolAddress((void**)&WT, g_WT);

    float* wtq  = WT;
    float* wtqr = WT + 1 * 1024 * 1024;
    float* wtkr = WT + 2 * 1024 * 1024;
    float* wto  = WT + 3 * 1024 * 1024;
    float* wtk  = WT + 4 * 1024 * 1024;
    float* wtv  = WT + 4 * 1024 * 1024 + 256 * 1024;

    // 0) transpose weights
    dim3 tb(32, 8);
    transpose_kernel<<<dim3(32, 32), tb>>>(wq_attn, wtq, 1024, 1024);
    transpose_kernel<<<dim3(32, 32), tb>>>(wq_rel, wtqr, 1024, 1024);
    transpose_kernel<<<dim3(32, 32), tb>>>(wk_rel, wtkr, 1024, 1024);
    transpose_kernel<<<dim3(32, 32), tb>>>(wo, wto, 1024, 1024);
    transpose_kernel<<<dim3(8, 32), tb>>>(wk_attn, wtk, 1024, 256);
    transpose_kernel<<<dim3(8, 32), tb>>>(wv, wtv, 1024, 256);

    // 1) fused projections on mma.sync tf32
    proj_mma_kernel<<<dim3(4, 56), 256>>>(x, symbols, wtq, wtqr, wtkr, wtk, wtv,
                                          Q, K, QR, KR, SV);

    // 2) RoPE
    rope_kernel<<<(L * NH * 32 + 255) / 256, 256>>>(Q, fcos, fsin, NH);
    rope_kernel<<<(L * NKV * 32 + 255) / 256, 256>>>(K, fcos, fsin, NKV);

    // 3) scores + softmax
    scores_kernel<<<dim3(8, 8, NH), 256>>>(Q, K, attn);
    softmax_kernel<<<NH * L, 256>>>(attn);

    // 4) relations
    relations_kernel<<<dim3(8, 8, NR), 256>>>(QR, KR, rel);

    // 5) S factorization
    s_kernel<<<L, 256>>>(attn, rel, S);

    // 6) ctx
    attended_kernel<<<dim3(8, NH), 256>>>(attn, SV, S, wr, CTX);

    // 7) out = ctx @ wo (tf32 mma)
    out_mma_kernel<<<dim3(4, 16), 256>>>(CTX, wto, out);
}

// round 5
// speedup vs baseline: 3.6740x; 1.2099x over previous
#include <cuda_runtime.h>
#include <cuda_bf16.h>
#include <cstdint>
#include <math.h>

#define L 512
#define Dm 1024
#define NH 16
#define NKV 4
#define NR 16
#define HD 64
#define ATTN_SCALE 0.125f
#define REL_SCALE 0.125f

// ---------------- scratch ----------------------------------------------------
__device__ float g_Q[L * NH * HD];
__device__ float g_K[L * NKV * HD];
__device__ float g_QR[L * NR * HD];
__device__ float g_KR[L * NR * HD];
__device__ float g_SV[L * NKV * HD];
__device__ float g_S[L * NH * NR];
__device__ float g_CTX[L * NH * HD];

__device__ __forceinline__ float to_tf32(float x) {
    uint32_t u;
    asm("cvt.rna.tf32.f32 %0, %1;" : "=r"(u) : "f"(x));
    return __uint_as_float(u);
}
__device__ __forceinline__ void mma_tf32(float c[4], uint32_t a0, uint32_t a1,
                                         uint32_t a2, uint32_t a3,
                                         uint32_t b0, uint32_t b1) {
    asm volatile(
        "mma.sync.aligned.m16n8k8.row.col.f32.tf32.tf32.f32 "
        "{%0,%1,%2,%3}, {%4,%5,%6,%7}, {%8,%9}, {%0,%1,%2,%3};"
        : "+f"(c[0]), "+f"(c[1]), "+f"(c[2]), "+f"(c[3])
        : "r"(a0), "r"(a1), "r"(a2), "r"(a3), "r"(b0), "r"(b1));
}

// ---------------- single-pass tf32 GEMM (projections / out) -----------------
// C[128,64] = A[M,K] @ W[K,N] slice. B staged [k][n]. 8 warps = 4m x 2n.
__device__ __forceinline__ void mma_gemm_tile(
    const float* __restrict__ A, int lda,
    const float* __restrict__ W, int ldb,
    float* __restrict__ C, int ldc,
    int m0, int n0, int K)
{
    __shared__ float As[128][36];   // [m][k]
    __shared__ float Bs[32][72];    // [k][n]

    int tid = threadIdx.x;
    int warp = tid >> 5, lane = tid & 31;
    int tq = lane >> 2, tr = lane & 3;
    int wm = warp & 3, wn = warp >> 2;
    int mb = wm * 32, nb = wn * 32;

    float c[2][4][4];
    #pragma unroll
    for (int i = 0; i < 2; i++)
        #pragma unroll
        for (int j = 0; j < 4; j++)
            #pragma unroll
            for (int k = 0; k < 4; k++) c[i][j][k] = 0.f;

    for (int k0 = 0; k0 < K; k0 += 32) {
        #pragma unroll
        for (int i = 0; i < 4; i++) {   // A: 128x32
            int e = tid + i * 256;
            int r = e >> 3, c4 = e & 7;
            float4 v = *reinterpret_cast<const float4*>(&A[(size_t)(m0 + r) * lda + k0 + c4 * 4]);
            v.x = to_tf32(v.x); v.y = to_tf32(v.y); v.z = to_tf32(v.z); v.w = to_tf32(v.w);
            *reinterpret_cast<float4*>(&As[r][c4 * 4]) = v;
        }
        #pragma unroll
        for (int i = 0; i < 2; i++) {   // B: 32x64 from [K,N], no pre-transpose
            int e = tid + i * 256;
            int k = e >> 4, n4 = e & 15;
            float4 v = *reinterpret_cast<const float4*>(&W[(size_t)(k0 + k) * ldb + n0 + n4 * 4]);
            v.x = to_tf32(v.x); v.y = to_tf32(v.y); v.z = to_tf32(v.z); v.w = to_tf32(v.w);
            *reinterpret_cast<float4*>(&Bs[k][n4 * 4]) = v;
        }
        __syncthreads();
        #pragma unroll
        for (int ks = 0; ks < 4; ks++) {
            int kb = ks * 8;
            uint32_t a[2][4], b[4][2];
            #pragma unroll
            for (int ma = 0; ma < 2; ma++) {
                int r0 = mb + ma * 16 + tq;
                a[ma][0] = __float_as_uint(As[r0][kb + tr]);
                a[ma][1] = __float_as_uint(As[r0 + 8][kb + tr]);
                a[ma][2] = __float_as_uint(As[r0][kb + tr + 4]);
                a[ma][3] = __float_as_uint(As[r0 + 8][kb + tr + 4]);
            }
            #pragma unroll
            for (int na = 0; na < 4; na++) {
                int n_ = nb + na * 8 + tq;
                b[na][0] = __float_as_uint(Bs[kb + tr][n_]);
                b[na][1] = __float_as_uint(Bs[kb + tr + 4][n_]);
            }
            #pragma unroll
            for (int ma = 0; ma < 2; ma++)
                #pragma unroll
                for (int na = 0; na < 4; na++)
                    mma_tf32(c[ma][na], a[ma][0], a[ma][1], a[ma][2], a[ma][3],
                             b[na][0], b[na][1]);
        }
        __syncthreads();
    }
    #pragma unroll
    for (int ma = 0; ma < 2; ma++) {
        int row = m0 + mb + ma * 16 + tq;
        #pragma unroll
        for (int na = 0; na < 4; na++) {
            int col = n0 + nb + na * 8 + 2 * tr;
            *reinterpret_cast<float2*>(&C[(size_t)row * ldc + col]) =
                make_float2(c[ma][na][0], c[ma][na][1]);
            *reinterpret_cast<float2*>(&C[(size_t)(row + 8) * ldc + col]) =
                make_float2(c[ma][na][2], c[ma][na][3]);
        }
    }
}

__global__ void __launch_bounds__(256, 2) proj_mma_kernel(
    const float* __restrict__ x, const float* __restrict__ symbols,
    const float* __restrict__ wq, const float* __restrict__ wqr,
    const float* __restrict__ wkr, const float* __restrict__ wk,
    const float* __restrict__ wv,
    float* __restrict__ Q, float* __restrict__ Kp, float* __restrict__ QR,
    float* __restrict__ KR, float* __restrict__ SV)
{
    int mt = blockIdx.x;
    int t = blockIdx.y;
    const float* A = x;
    const float* W;
    float* C;
    int ldb, n0;
    if (t < 16)      { W = wq;  C = Q;  ldb = 1024; n0 = t * 64; }
    else if (t < 32) { W = wqr; C = QR; ldb = 1024; n0 = (t - 16) * 64; }
    else if (t < 48) { W = wkr; C = KR; ldb = 1024; n0 = (t - 32) * 64; }
    else if (t < 52) { W = wk;  C = Kp; ldb = 256;  n0 = (t - 48) * 64; }
    else             { W = wv; A = symbols; C = SV; ldb = 256; n0 = (t - 52) * 64; }
    mma_gemm_tile(A, 1024, W, ldb, C, ldb, mt * 128, n0, 1024);
}

__global__ void __launch_bounds__(256, 2) out_mma_kernel(
    const float* __restrict__ CTX, const float* __restrict__ wo, float* __restrict__ out)
{
    mma_gemm_tile(CTX, 1024, wo, 1024, out, 1024, blockIdx.x * 128, blockIdx.y * 64, 1024);
}

// ---------------- 3xTF32 compute core ----------------------------------------
// BNK=1: B stored [n][k] rows at n0 (scores/relations: keys are [j][d]).
// BNK=0: B stored [k][n], cols at n0 (attended: sv is [j][d] with k=j).
template<int BNK>
__device__ __forceinline__ void mma3x_compute(
    const float* __restrict__ A, int lda,
    const float* __restrict__ B, int ldb,
    int m0, int n0, int kmax, float c[2][4][4])
{
    constexpr int BR = BNK ? 64 : 16;
    constexpr int BC = BNK ? 20 : 72;
    __shared__ float As_hi[128][20], As_lo[128][20];
    __shared__ float Bs_hi[BR][BC], Bs_lo[BR][BC];

    int tid = threadIdx.x;
    int warp = tid >> 5, lane = tid & 31;
    int tq = lane >> 2, tr = lane & 3;
    int wm = warp & 3, wn = warp >> 2;
    int mb = wm * 32, nb = wn * 32;

    for (int k0 = 0; k0 < kmax; k0 += 16) {
        #pragma unroll
        for (int i = 0; i < 2; i++) {   // A: 128x16
            int e = tid + i * 256;
            int r = e >> 2, k4 = e & 3;
            float4 v = *reinterpret_cast<const float4*>(&A[(size_t)(m0 + r) * lda + k0 + k4 * 4]);
            float4 h = make_float4(to_tf32(v.x), to_tf32(v.y), to_tf32(v.z), to_tf32(v.w));
            float4 l = make_float4(to_tf32(v.x - h.x), to_tf32(v.y - h.y),
                                   to_tf32(v.z - h.z), to_tf32(v.w - h.w));
            *reinterpret_cast<float4*>(&As_hi[r][k4 * 4]) = h;
            *reinterpret_cast<float4*>(&As_lo[r][k4 * 4]) = l;
        }
        {
            if (BNK) {                  // B: 64 rows x 16 k
                int r = tid >> 2, k4 = tid & 3;
                float4 v = *reinterpret_cast<const float4*>(&B[(size_t)(n0 + r) * ldb + k0 + k4 * 4]);
                float4 h = make_float4(to_tf32(v.x), to_tf32(v.y), to_tf32(v.z), to_tf32(v.w));
                float4 l = make_float4(to_tf32(v.x - h.x), to_tf32(v.y - h.y),
                                       to_tf32(v.z - h.z), to_tf32(v.w - h.w));
                *reinterpret_cast<float4*>(&Bs_hi[r][k4 * 4]) = h;
                *reinterpret_cast<float4*>(&Bs_lo[r][k4 * 4]) = l;
            } else {                    // B: 16 k x 64 n
                int k = tid >> 4, n4 = tid & 15;
                float4 v = *reinterpret_cast<const float4*>(&B[(size_t)(k0 + k) * ldb + n0 + n4 * 4]);
                float4 h = make_float4(to_tf32(v.x), to_tf32(v.y), to_tf32(v.z), to_tf32(v.w));
                float4 l = make_float4(to_tf32(v.x - h.x), to_tf32(v.y - h.y),
                                       to_tf32(v.z - h.z), to_tf32(v.w - h.w));
                *reinterpret_cast<float4*>(&Bs_hi[k][n4 * 4]) = h;
                *reinterpret_cast<float4*>(&Bs_lo[k][n4 * 4]) = l;
            }
        }
        __syncthreads();
        #pragma unroll
        for (int ks = 0; ks < 2; ks++) {
            int kb = ks * 8;
            uint32_t ah[2][4], al[2][4], bh[4][2], bl[4][2];
            #pragma unroll
            for (int ma = 0; ma < 2; ma++) {
                int r0 = mb + ma * 16 + tq;
                ah[ma][0] = __float_as_uint(As_hi[r0][kb + tr]);
                ah[ma][1] = __float_as_uint(As_hi[r0 + 8][kb + tr]);
                ah[ma][2] = __float_as_uint(As_hi[r0][kb + tr + 4]);
                ah[ma][3] = __float_as_uint(As_hi[r0 + 8][kb + tr + 4]);
                al[ma][0] = __float_as_uint(As_lo[r0][kb + tr]);
                al[ma][1] = __float_as_uint(As_lo[r0 + 8][kb + tr]);
                al[ma][2] = __float_as_uint(As_lo[r0][kb + tr + 4]);
                al[ma][3] = __float_as_uint(As_lo[r0 + 8][kb + tr + 4]);
            }
            #pragma unroll
            for (int na = 0; na < 4; na++) {
                int n_ = nb + na * 8 + tq;
                if (BNK) {
                    bh[na][0] = __float_as_uint(Bs_hi[n_][kb + tr]);
                    bh[na][1] = __float_as_uint(Bs_hi[n_][kb + tr + 4]);
                    bl[na][0] = __float_as_uint(Bs_lo[n_][kb + tr]);
                    bl[na][1] = __float_as_uint(Bs_lo[n_][kb + tr + 4]);
                } else {
                    bh[na][0] = __float_as_uint(Bs_hi[kb + tr][n_]);
                    bh[na][1] = __float_as_uint(Bs_hi[kb + tr + 4][n_]);
                    bl[na][0] = __float_as_uint(Bs_lo[kb + tr][n_]);
                    bl[na][1] = __float_as_uint(Bs_lo[kb + tr + 4][n_]);
                }
            }
            #pragma unroll
            for (int ma = 0; ma < 2; ma++)
                #pragma unroll
                for (int na = 0; na < 4; na++) {
                    mma_tf32(c[ma][na], ah[ma][0], ah[ma][1], ah[ma][2], ah[ma][3],
                             bl[na][0], bl[na][1]);
                    mma_tf32(c[ma][na], al[ma][0], al[ma][1], al[ma][2], al[ma][3],
                             bh[na][0], bh[na][1]);
                    mma_tf32(c[ma][na], ah[ma][0], ah[ma][1], ah[ma][2], ah[ma][3],
                             bh[na][0], bh[na][1]);
                }
        }
        __syncthreads();
    }
}

// ---------------- scores (3xTF32, causal-tile skip) --------------------------
__global__ void __launch_bounds__(256, 2) scores3x_kernel(
    const float* __restrict__ Q, const float* __restrict__ K, float* __restrict__ attn)
{
    int h = blockIdx.z;
    int m0 = blockIdx.y * 128, n0 = blockIdx.x * 64;
    if (n0 >= m0 + 128) return;

    float c[2][4][4];
    #pragma unroll
    for (int i = 0; i < 2; i++)
        #pragma unroll
        for (int j = 0; j < 4; j++)
            #pragma unroll
            for (int k = 0; k < 4; k++) c[i][j][k] = 0.f;

    mma3x_compute<1>(Q + h * HD, 1024, K + (h >> 2) * HD, 256, m0, n0, 64, c);

    int lane = threadIdx.x & 31, warp = threadIdx.x >> 5;
    int tq = lane >> 2, tr = lane & 3;
    int mb = (warp & 3) * 32, nb = (warp >> 2) * 32;
    float* C = attn + (size_t)h * L * L;
    #pragma unroll
    for (int ma = 0; ma < 2; ma++) {
        int row = m0 + mb + ma * 16 + tq;
        #pragma unroll
        for (int na = 0; na < 4; na++) {
            int col = n0 + nb + na * 8 + 2 * tr;
            *reinterpret_cast<float2*>(&C[(size_t)row * L + col]) =
                make_float2(c[ma][na][0] * ATTN_SCALE, c[ma][na][1] * ATTN_SCALE);
            *reinterpret_cast<float2*>(&C[(size_t)(row + 8) * L + col]) =
                make_float2(c[ma][na][2] * ATTN_SCALE, c[ma][na][3] * ATTN_SCALE);
        }
    }
}

// ---------------- relations (3xTF32, strided scatter epilogue) ---------------
__global__ void __launch_bounds__(256, 2) relations3x_kernel(
    const float* __restrict__ QR, const float* __restrict__ KR, float* __restrict__ rel)
{
    int r = blockIdx.z;
    int m0 = blockIdx.y * 128, n0 = blockIdx.x * 64;

    float c[2][4][4];
    #pragma unroll
    for (int i = 0; i < 2; i++)
        #pragma unroll
        for (int j = 0; j < 4; j++)
            #pragma unroll
            for (int k = 0; k < 4; k++) c[i][j][k] = 0.f;

    mma3x_compute<1>(QR + r * HD, 1024, KR + r * HD, 1024, m0, n0, 64, c);

    int lane = threadIdx.x & 31, warp = threadIdx.x >> 5;
    int tq = lane >> 2, tr = lane & 3;
    int mb = (warp & 3) * 32, nb = (warp >> 2) * 32;
    #pragma unroll
    for (int ma = 0; ma < 2; ma++) {
        int row = m0 + mb + ma * 16 + tq;
        #pragma unroll
        for (int na = 0; na < 4; na++) {
            int col = n0 + nb + na * 8 + 2 * tr;
            rel[((size_t)row * L + col) * NR + r]           = c[ma][na][0] * REL_SCALE;
            rel[((size_t)row * L + col + 1) * NR + r]       = c[ma][na][1] * REL_SCALE;
            rel[((size_t)(row + 8) * L + col) * NR + r]     = c[ma][na][2] * REL_SCALE;
            rel[((size_t)(row + 8) * L + col + 1) * NR + r] = c[ma][na][3] * REL_SCALE;
        }
    }
}

// ---------------- attended (3xTF32 attn@sv + S@wr epilogue) ------------------
__global__ void __launch_bounds__(256, 2) attended3x_kernel(
    const float* __restrict__ attn, const float* __restrict__ SV,
    const float* __restrict__ S, const float* __restrict__ wr,
    float* __restrict__ ctx)
{
    int h = blockIdx.y;
    int m0 = blockIdx.x * 128;
    int jmax = m0 + 128;   // causal: softmax zero-fills j>i so truncation is exact

    float c[2][4][4];
    #pragma unroll
    for (int i = 0; i < 2; i++)
        #pragma unroll
        for (int j = 0; j < 4; j++)
            #pragma unroll
            for (int k = 0; k < 4; k++) c[i][j][k] = 0.f;

    mma3x_compute<0>(attn + (size_t)h * L * L, L, SV + (h >> 2) * HD, 256, m0, 0, jmax, c);

    // S @ wr epilogue
    __shared__ float wrs[16][64];
    __shared__ float Ss[128][17];
    int tid = threadIdx.x;
    for (int t = tid; t < 16 * 64; t += 256) {
        int rr = t >> 6, n = t & 63;
        wrs[rr][n] = wr[(size_t)rr * (NH * HD) + h * HD + n];
    }
    for (int t = tid; t < 128 * 16; t += 256) {
        int m = t >> 4, rr = t & 15;
        Ss[m][rr] = S[((size_t)(m0 + m) * NH + h) * NR + rr];
    }
    __syncthreads();

    int lane = tid & 31, warp = tid >> 5;
    int tq = lane >> 2, tr = lane & 3;
    int mb = (warp & 3) * 32, nb = (warp >> 2) * 32;
    #pragma unroll
    for (int rr = 0; rr < 16; rr++) {
        #pragma unroll
        for (int ma = 0; ma < 2; ma++) {
            float s0 = Ss[mb + ma * 16 + tq][rr];
            float s1 = Ss[mb + ma * 16 + tq + 8][rr];
            #pragma unroll
            for (int na = 0; na < 4; na++) {
                int col = nb + na * 8 + 2 * tr;
                float w0 = wrs[rr][col], w1 = wrs[rr][col + 1];
                c[ma][na][0] += s0 * w0; c[ma][na][1] += s0 * w1;
                c[ma][na][2] += s1 * w0; c[ma][na][3] += s1 * w1;
            }
        }
    }
    #pragma unroll
    for (int ma = 0; ma < 2; ma++) {
        int row = m0 + mb + ma * 16 + tq;
        #pragma unroll
        for (int na = 0; na < 4; na++) {
            int col = h * HD + nb + na * 8 + 2 * tr;
            *reinterpret_cast<float2*>(&ctx[(size_t)row * (NH * HD) + col]) =
                make_float2(c[ma][na][0], c[ma][na][1]);
            *reinterpret_cast<float2*>(&ctx[(size_t)(row + 8) * (NH * HD) + col]) =
                make_float2(c[ma][na][2], c[ma][na][3]);
        }
    }
}

// ---------------- RoPE -------------------------------------------------------
__global__ void rope_kernel(float* __restrict__ t, const float* __restrict__ pcos,
                            const float* __restrict__ psin, int nheads) {
    int idx = blockIdx.x * blockDim.x + threadIdx.x;
    int total = L * nheads * (HD / 2);
    if (idx >= total) return;
    int p = idx & 31;
    int rest = idx >> 5;
    int hh = rest % nheads;
    int i = rest / nheads;
    float c = pcos[i * 32 + p], s = psin[i * 32 + p];
    float* base = t + ((size_t)i * nheads + hh) * HD + 2 * p;
    float re = base[0], im = base[1];
    base[0] = re * c - im * s;
    base[1] = re * s + im * c;
}

// ---------------- causal softmax ---------------------------------------------
__global__ void softmax_kernel(float* __restrict__ attn) {
    int row = blockIdx.x;
    int i = row & (L - 1);
    float* p = attn + (size_t)row * L;
    int len = i + 1;
    int tid = threadIdx.x;
    __shared__ float rowv[L];
    __shared__ float red[256];
    for (int j = tid; j < L; j += 256) rowv[j] = (j < len) ? p[j] : -3.0e38f;
    __syncthreads();
    float m = -3.0e38f;
    for (int j = tid; j < L; j += 256) m = fmaxf(m, rowv[j]);
    red[tid] = m; __syncthreads();
    for (int s = 128; s > 0; s >>= 1) { if (tid < s) red[tid] = fmaxf(red[tid], red[tid + s]); __syncthreads(); }
    m = red[0]; __syncthreads();
    float sum = 0.f;
    for (int j = tid; j < L; j += 256) {
        float e = (j < len) ? __expf(rowv[j] - m) : 0.f;
        rowv[j] = e;
        sum += e;
    }
    red[tid] = sum; __syncthreads();
    for (int s = 128; s > 0; s >>= 1) { if (tid < s) red[tid] += red[tid + s]; __syncthreads(); }
    float inv = 1.f / red[0];
    for (int j = tid; j < L; j += 256) p[j] = (j < len) ? rowv[j] * inv : 0.f;
}

// ---------------- S[i,h,r] = sum_j attn[h,i,j] * rel[i,j,r] ------------------
__global__ void s_kernel(const float* __restrict__ attn, const float* __restrict__ rel,
                         float* __restrict__ S) {
    int i = blockIdx.x;
    int tid = threadIdx.x;
    int h = tid >> 4, r = tid & 15;
    __shared__ float attnS[16][128];
    float acc = 0.f;
    int len = i + 1;
    for (int j0 = 0; j0 < len; j0 += 128) {
        int n = min(128, len - j0);
        for (int t = tid; t < 16 * 128; t += 256) {
            int hh = t >> 7, jj = t & 127;
            attnS[hh][jj] = (jj < n) ? attn[((size_t)hh * L + i) * L + j0 + jj] : 0.f;
        }
        __syncthreads();
        for (int jj = 0; jj < n; jj++)
            acc += attnS[h][jj] * rel[((size_t)i * L + j0 + jj) * NR + r];
        __syncthreads();
    }
    S[((size_t)i * NH + h) * NR + r] = acc;
}

// ---------------------------------------------------------------------------
extern "C" void kernel_launch(void* const* d_in, const int* in_sizes, int n_in,
                              void* d_out, int out_size) {
    const float* x       = (const float*)d_in[0];
    const float* symbols = (const float*)d_in[1];
    const float* fcos    = (const float*)d_in[2];
    const float* fsin    = (const float*)d_in[3];
    const float* wq_attn = (const float*)d_in[4];
    const float* wk_attn = (const float*)d_in[5];
    const float* wq_rel  = (const float*)d_in[6];
    const float* wk_rel  = (const float*)d_in[7];
    const float* wr      = (const float*)d_in[8];
    const float* wv      = (const float*)d_in[9];
    const float* wo      = (const float*)d_in[10];

    float* out  = (float*)d_out;
    float* attn = out + (size_t)L * NH * HD;
    float* rel  = attn + (size_t)NH * L * L;

    float *Q, *K, *QR, *KR, *SV, *S, *CTX;
    cudaGetSymbolAddress((void**)&Q,  g_Q);
    cudaGetSymbolAddress((void**)&K,  g_K);
    cudaGetSymbolAddress((void**)&QR, g_QR);
    cudaGetSymbolAddress((void**)&KR, g_KR);
    cudaGetSymbolAddress((void**)&SV, g_SV);
    cudaGetSymbolAddress((void**)&S,  g_S);
    cudaGetSymbolAddress((void**)&CTX, g_CTX);

    // 1) projections (direct weights, no transposes)
    proj_mma_kernel<<<dim3(4, 56), 256>>>(x, symbols, wq_attn, wq_rel, wk_rel,
                                          wk_attn, wv, Q, K, QR, KR, SV);

    // 2) RoPE
    rope_kernel<<<(L * NH * 32 + 255) / 256, 256>>>(Q, fcos, fsin, NH);
    rope_kernel<<<(L * NKV * 32 + 255) / 256, 256>>>(K, fcos, fsin, NKV);

    // 3) scores (3xTF32) + softmax
    scores3x_kernel<<<dim3(8, 4, NH), 256>>>(Q, K, attn);
    softmax_kernel<<<NH * L, 256>>>(attn);

    // 4) relations (3xTF32)
    relations3x_kernel<<<dim3(8, 4, NR), 256>>>(QR, KR, rel);

    // 5) S factorization
    s_kernel<<<L, 256>>>(attn, rel, S);

    // 6) ctx = attn@sv (3xTF32) + S@wr
    attended3x_kernel<<<dim3(4, NH), 256>>>(attn, SV, S, wr, CTX);

    // 7) out = ctx @ wo
    out_mma_kernel<<<dim3(4, 16), 256>>>(CTX, wo, out);
}

// round 6
// speedup vs baseline: 4.3597x; 1.1866x over previous
#include <cuda_runtime.h>
#include <cuda_bf16.h>
#include <cstdint>
#include <math.h>

#define L 512
#define Dm 1024
#define NH 16
#define NKV 4
#define NR 16
#define HD 64
#define ATTN_SCALE 0.125f
#define REL_SCALE 0.125f

// ---------------- scratch ----------------------------------------------------
__device__ float g_Q[L * NH * HD];
__device__ float g_K[L * NKV * HD];
__device__ float g_QR[L * NR * HD];
__device__ float g_KR[L * NR * HD];
__device__ float g_SV[L * NKV * HD];
__device__ float g_S[L * NH * NR];
__device__ float g_CTX[L * NH * HD];

__device__ __forceinline__ float to_tf32(float x) {
    uint32_t u;
    asm("cvt.rna.tf32.f32 %0, %1;" : "=r"(u) : "f"(x));
    return __uint_as_float(u);
}
__device__ __forceinline__ void mma_tf32(float c[4], uint32_t a0, uint32_t a1,
                                         uint32_t a2, uint32_t a3,
                                         uint32_t b0, uint32_t b1) {
    asm volatile(
        "mma.sync.aligned.m16n8k8.row.col.f32.tf32.tf32.f32 "
        "{%0,%1,%2,%3}, {%4,%5,%6,%7}, {%8,%9}, {%0,%1,%2,%3};"
        : "+f"(c[0]), "+f"(c[1]), "+f"(c[2]), "+f"(c[3])
        : "r"(a0), "r"(a1), "r"(a2), "r"(a3), "r"(b0), "r"(b1));
}

// ---------------- pipelined tf32 GEMM tile (projections / out) ---------------
// C[128,64] = A[M,K] @ W[K,N] slice; register-prefetch double buffering.
// Optional fused RoPE on the 64-col output (ropef != 0).
__device__ __forceinline__ void mma_gemm_tile(
    const float* __restrict__ A, int lda,
    const float* __restrict__ W, int ldb,
    float* __restrict__ C, int ldc,
    int m0, int n0, int K,
    const float* __restrict__ fcos, const float* __restrict__ fsin, int ropef)
{
    __shared__ float As[128][36];   // [m][k]
    __shared__ float Bs[32][72];    // [k][n]

    int tid = threadIdx.x;
    int warp = tid >> 5, lane = tid & 31;
    int tq = lane >> 2, tr = lane & 3;
    int wm = warp & 3, wn = warp >> 2;
    int mb = wm * 32, nb = wn * 32;

    // per-thread load coords
    int ar = tid >> 1;                 // with i-offset below: A rows
    int ac4 = (tid & 1) * 4;           // not used; explicit mapping kept below

    float c[2][4][4];
    #pragma unroll
    for (int i = 0; i < 2; i++)
        #pragma unroll
        for (int j = 0; j < 4; j++)
            #pragma unroll
            for (int k = 0; k < 4; k++) c[i][j][k] = 0.f;

    float4 pa[4], pb[2];
    // prefetch chunk 0
    #pragma unroll
    for (int i = 0; i < 4; i++) {
        int e = tid + i * 256;
        int r = e >> 3, c4 = e & 7;
        pa[i] = *reinterpret_cast<const float4*>(&A[(size_t)(m0 + r) * lda + c4 * 4]);
    }
    #pragma unroll
    for (int i = 0; i < 2; i++) {
        int e = tid + i * 256;
        int k = e >> 4, n4 = e & 15;
        pb[i] = *reinterpret_cast<const float4*>(&W[(size_t)k * ldb + n0 + n4 * 4]);
    }

    int nch = K >> 5;
    for (int kc = 0; kc < nch; kc++) {
        // commit prefetched chunk to smem (with rna tf32 conversion)
        #pragma unroll
        for (int i = 0; i < 4; i++) {
            int e = tid + i * 256;
            int r = e >> 3, c4 = e & 7;
            float4 v = pa[i];
            v.x = to_tf32(v.x); v.y = to_tf32(v.y); v.z = to_tf32(v.z); v.w = to_tf32(v.w);
            *reinterpret_cast<float4*>(&As[r][c4 * 4]) = v;
        }
        #pragma unroll
        for (int i = 0; i < 2; i++) {
            int e = tid + i * 256;
            int k = e >> 4, n4 = e & 15;
            float4 v = pb[i];
            v.x = to_tf32(v.x); v.y = to_tf32(v.y); v.z = to_tf32(v.z); v.w = to_tf32(v.w);
            *reinterpret_cast<float4*>(&Bs[k][n4 * 4]) = v;
        }
        __syncthreads();
        // issue next chunk's loads (in flight during compute)
        if (kc + 1 < nch) {
            int k0n = (kc + 1) << 5;
            #pragma unroll
            for (int i = 0; i < 4; i++) {
                int e = tid + i * 256;
                int r = e >> 3, c4 = e & 7;
                pa[i] = *reinterpret_cast<const float4*>(&A[(size_t)(m0 + r) * lda + k0n + c4 * 4]);
            }
            #pragma unroll
            for (int i = 0; i < 2; i++) {
                int e = tid + i * 256;
                int k = e >> 4, n4 = e & 15;
                pb[i] = *reinterpret_cast<const float4*>(&W[(size_t)(k0n + k) * ldb + n0 + n4 * 4]);
            }
        }
        #pragma unroll
        for (int ks = 0; ks < 4; ks++) {
            int kb = ks * 8;
            uint32_t a[2][4], b[4][2];
            #pragma unroll
            for (int ma = 0; ma < 2; ma++) {
                int r0 = mb + ma * 16 + tq;
                a[ma][0] = __float_as_uint(As[r0][kb + tr]);
                a[ma][1] = __float_as_uint(As[r0 + 8][kb + tr]);
                a[ma][2] = __float_as_uint(As[r0][kb + tr + 4]);
                a[ma][3] = __float_as_uint(As[r0 + 8][kb + tr + 4]);
            }
            #pragma unroll
            for (int na = 0; na < 4; na++) {
                int n_ = nb + na * 8 + tq;
                b[na][0] = __float_as_uint(Bs[kb + tr][n_]);
                b[na][1] = __float_as_uint(Bs[kb + tr + 4][n_]);
            }
            #pragma unroll
            for (int ma = 0; ma < 2; ma++)
                #pragma unroll
                for (int na = 0; na < 4; na++)
                    mma_tf32(c[ma][na], a[ma][0], a[ma][1], a[ma][2], a[ma][3],
                             b[na][0], b[na][1]);
        }
        __syncthreads();
    }

    #pragma unroll
    for (int ma = 0; ma < 2; ma++) {
        int row = m0 + mb + ma * 16 + tq;
        #pragma unroll
        for (int na = 0; na < 4; na++) {
            int col = n0 + nb + na * 8 + 2 * tr;
            float v0 = c[ma][na][0], v1 = c[ma][na][1];
            float v2 = c[ma][na][2], v3 = c[ma][na][3];
            if (ropef) {   // (v0,v1)=(re,im) at row; (v2,v3) at row+8
                int p = (col & 63) >> 1;
                float c0 = fcos[row * 32 + p], s0 = fsin[row * 32 + p];
                float c1 = fcos[(row + 8) * 32 + p], s1 = fsin[(row + 8) * 32 + p];
                float t0 = v0 * c0 - v1 * s0, t1 = v0 * s0 + v1 * c0;
                float t2 = v2 * c1 - v3 * s1, t3 = v2 * s1 + v3 * c1;
                v0 = t0; v1 = t1; v2 = t2; v3 = t3;
            }
            *reinterpret_cast<float2*>(&C[(size_t)row * ldc + col]) = make_float2(v0, v1);
            *reinterpret_cast<float2*>(&C[(size_t)(row + 8) * ldc + col]) = make_float2(v2, v3);
        }
    }
}

__global__ void __launch_bounds__(256, 2) proj_mma_kernel(
    const float* __restrict__ x, const float* __restrict__ symbols,
    const float* __restrict__ wq, const float* __restrict__ wqr,
    const float* __restrict__ wkr, const float* __restrict__ wk,
    const float* __restrict__ wv,
    const float* __restrict__ fcos, const float* __restrict__ fsin,
    float* __restrict__ Q, float* __restrict__ Kp, float* __restrict__ QR,
    float* __restrict__ KR, float* __restrict__ SV)
{
    int mt = blockIdx.x;
    int t = blockIdx.y;
    const float* A = x;
    const float* W;
    float* C;
    int ldb, n0, ropef = 0;
    if (t < 16)      { W = wq;  C = Q;  ldb = 1024; n0 = t * 64; ropef = 1; }
    else if (t < 32) { W = wqr; C = QR; ldb = 1024; n0 = (t - 16) * 64; }
    else if (t < 48) { W = wkr; C = KR; ldb = 1024; n0 = (t - 32) * 64; }
    else if (t < 52) { W = wk;  C = Kp; ldb = 256;  n0 = (t - 48) * 64; ropef = 1; }
    else             { W = wv; A = symbols; C = SV; ldb = 256; n0 = (t - 52) * 64; }
    mma_gemm_tile(A, 1024, W, ldb, C, ldb, mt * 128, n0, 1024, fcos, fsin, ropef);
}

__global__ void __launch_bounds__(256, 2) out_mma_kernel(
    const float* __restrict__ CTX, const float* __restrict__ wo, float* __restrict__ out)
{
    mma_gemm_tile(CTX, 1024, wo, 1024, out, 1024, blockIdx.x * 128, blockIdx.y * 64, 1024,
                  nullptr, nullptr, 0);
}

// ---------------- 3xTF32 compute core (unchanged) ----------------------------
template<int BNK>
__device__ __forceinline__ void mma3x_compute(
    const float* __restrict__ A, int lda,
    const float* __restrict__ B, int ldb,
    int m0, int n0, int kmax, float c[2][4][4])
{
    constexpr int BR = BNK ? 64 : 16;
    constexpr int BC = BNK ? 20 : 72;
    __shared__ float As_hi[128][20], As_lo[128][20];
    __shared__ float Bs_hi[BR][BC], Bs_lo[BR][BC];

    int tid = threadIdx.x;
    int warp = tid >> 5, lane = tid & 31;
    int tq = lane >> 2, tr = lane & 3;
    int wm = warp & 3, wn = warp >> 2;
    int mb = wm * 32, nb = wn * 32;

    for (int k0 = 0; k0 < kmax; k0 += 16) {
        #pragma unroll
        for (int i = 0; i < 2; i++) {
            int e = tid + i * 256;
            int r = e >> 2, k4 = e & 3;
            float4 v = *reinterpret_cast<const float4*>(&A[(size_t)(m0 + r) * lda + k0 + k4 * 4]);
            float4 h = make_float4(to_tf32(v.x), to_tf32(v.y), to_tf32(v.z), to_tf32(v.w));
            float4 l = make_float4(to_tf32(v.x - h.x), to_tf32(v.y - h.y),
                                   to_tf32(v.z - h.z), to_tf32(v.w - h.w));
            *reinterpret_cast<float4*>(&As_hi[r][k4 * 4]) = h;
            *reinterpret_cast<float4*>(&As_lo[r][k4 * 4]) = l;
        }
        {
            if (BNK) {
                int r = tid >> 2, k4 = tid & 3;
                float4 v = *reinterpret_cast<const float4*>(&B[(size_t)(n0 + r) * ldb + k0 + k4 * 4]);
                float4 h = make_float4(to_tf32(v.x), to_tf32(v.y), to_tf32(v.z), to_tf32(v.w));
                float4 l = make_float4(to_tf32(v.x - h.x), to_tf32(v.y - h.y),
                                       to_tf32(v.z - h.z), to_tf32(v.w - h.w));
                *reinterpret_cast<float4*>(&Bs_hi[r][k4 * 4]) = h;
                *reinterpret_cast<float4*>(&Bs_lo[r][k4 * 4]) = l;
            } else {
                int k = tid >> 4, n4 = tid & 15;
                float4 v = *reinterpret_cast<const float4*>(&B[(size_t)(k0 + k) * ldb + n0 + n4 * 4]);
                float4 h = make_float4(to_tf32(v.x), to_tf32(v.y), to_tf32(v.z), to_tf32(v.w));
                float4 l = make_float4(to_tf32(v.x - h.x), to_tf32(v.y - h.y),
                                       to_tf32(v.z - h.z), to_tf32(v.w - h.w));
                *reinterpret_cast<float4*>(&Bs_hi[k][n4 * 4]) = h;
                *reinterpret_cast<float4*>(&Bs_lo[k][n4 * 4]) = l;
            }
        }
        __syncthreads();
        #pragma unroll
        for (int ks = 0; ks < 2; ks++) {
            int kb = ks * 8;
            uint32_t ah[2][4], al[2][4], bh[4][2], bl[4][2];
            #pragma unroll
            for (int ma = 0; ma < 2; ma++) {
                int r0 = mb + ma * 16 + tq;
                ah[ma][0] = __float_as_uint(As_hi[r0][kb + tr]);
                ah[ma][1] = __float_as_uint(As_hi[r0 + 8][kb + tr]);
                ah[ma][2] = __float_as_uint(As_hi[r0][kb + tr + 4]);
                ah[ma][3] = __float_as_uint(As_hi[r0 + 8][kb + tr + 4]);
                al[ma][0] = __float_as_uint(As_lo[r0][kb + tr]);
                al[ma][1] = __float_as_uint(As_lo[r0 + 8][kb + tr]);
                al[ma][2] = __float_as_uint(As_lo[r0][kb + tr + 4]);
                al[ma][3] = __float_as_uint(As_lo[r0 + 8][kb + tr + 4]);
            }
            #pragma unroll
            for (int na = 0; na < 4; na++) {
                int n_ = nb + na * 8 + tq;
                if (BNK) {
                    bh[na][0] = __float_as_uint(Bs_hi[n_][kb + tr]);
                    bh[na][1] = __float_as_uint(Bs_hi[n_][kb + tr + 4]);
                    bl[na][0] = __float_as_uint(Bs_lo[n_][kb + tr]);
                    bl[na][1] = __float_as_uint(Bs_lo[n_][kb + tr + 4]);
                } else {
                    bh[na][0] = __float_as_uint(Bs_hi[kb + tr][n_]);
                    bh[na][1] = __float_as_uint(Bs_hi[kb + tr + 4][n_]);
                    bl[na][0] = __float_as_uint(Bs_lo[kb + tr][n_]);
                    bl[na][1] = __float_as_uint(Bs_lo[kb + tr + 4][n_]);
                }
            }
            #pragma unroll
            for (int ma = 0; ma < 2; ma++)
                #pragma unroll
                for (int na = 0; na < 4; na++) {
                    mma_tf32(c[ma][na], ah[ma][0], ah[ma][1], ah[ma][2], ah[ma][3],
                             bl[na][0], bl[na][1]);
                    mma_tf32(c[ma][na], al[ma][0], al[ma][1], al[ma][2], al[ma][3],
                             bh[na][0], bh[na][1]);
                    mma_tf32(c[ma][na], ah[ma][0], ah[ma][1], ah[ma][2], ah[ma][3],
                             bh[na][0], bh[na][1]);
                }
        }
        __syncthreads();
    }
}

// ---------------- scores (3xTF32) --------------------------------------------
__global__ void __launch_bounds__(256, 2) scores3x_kernel(
    const float* __restrict__ Q, const float* __restrict__ K, float* __restrict__ attn)
{
    int h = blockIdx.z;
    int m0 = blockIdx.y * 128, n0 = blockIdx.x * 64;
    if (n0 >= m0 + 128) return;

    float c[2][4][4];
    #pragma unroll
    for (int i = 0; i < 2; i++)
        #pragma unroll
        for (int j = 0; j < 4; j++)
            #pragma unroll
            for (int k = 0; k < 4; k++) c[i][j][k] = 0.f;

    mma3x_compute<1>(Q + h * HD, 1024, K + (h >> 2) * HD, 256, m0, n0, 64, c);

    int lane = threadIdx.x & 31, warp = threadIdx.x >> 5;
    int tq = lane >> 2, tr = lane & 3;
    int mb = (warp & 3) * 32, nb = (warp >> 2) * 32;
    float* C = attn + (size_t)h * L * L;
    #pragma unroll
    for (int ma = 0; ma < 2; ma++) {
        int row = m0 + mb + ma * 16 + tq;
        #pragma unroll
        for (int na = 0; na < 4; na++) {
            int col = n0 + nb + na * 8 + 2 * tr;
            *reinterpret_cast<float2*>(&C[(size_t)row * L + col]) =
                make_float2(c[ma][na][0] * ATTN_SCALE, c[ma][na][1] * ATTN_SCALE);
            *reinterpret_cast<float2*>(&C[(size_t)(row + 8) * L + col]) =
                make_float2(c[ma][na][2] * ATTN_SCALE, c[ma][na][3] * ATTN_SCALE);
        }
    }
}

// ---------------- relations (3xTF32) -----------------------------------------
__global__ void __launch_bounds__(256, 2) relations3x_kernel(
    const float* __restrict__ QR, const float* __restrict__ KR, float* __restrict__ rel)
{
    int r = blockIdx.z;
    int m0 = blockIdx.y * 128, n0 = blockIdx.x * 64;

    float c[2][4][4];
    #pragma unroll
    for (int i = 0; i < 2; i++)
        #pragma unroll
        for (int j = 0; j < 4; j++)
            #pragma unroll
            for (int k = 0; k < 4; k++) c[i][j][k] = 0.f;

    mma3x_compute<1>(QR + r * HD, 1024, KR + r * HD, 1024, m0, n0, 64, c);

    int lane = threadIdx.x & 31, warp = threadIdx.x >> 5;
    int tq = lane >> 2, tr = lane & 3;
    int mb = (warp & 3) * 32, nb = (warp >> 2) * 32;
    #pragma unroll
    for (int ma = 0; ma < 2; ma++) {
        int row = m0 + mb + ma * 16 + tq;
        #pragma unroll
        for (int na = 0; na < 4; na++) {
            int col = n0 + nb + na * 8 + 2 * tr;
            rel[((size_t)row * L + col) * NR + r]           = c[ma][na][0] * REL_SCALE;
            rel[((size_t)row * L + col + 1) * NR + r]       = c[ma][na][1] * REL_SCALE;
            rel[((size_t)(row + 8) * L + col) * NR + r]     = c[ma][na][2] * REL_SCALE;
            rel[((size_t)(row + 8) * L + col + 1) * NR + r] = c[ma][na][3] * REL_SCALE;
        }
    }
}

// ---------------- attended (3xTF32 attn@sv + S@wr) ---------------------------
__global__ void __launch_bounds__(256, 2) attended3x_kernel(
    const float* __restrict__ attn, const float* __restrict__ SV,
    const float* __restrict__ S, const float* __restrict__ wr,
    float* __restrict__ ctx)
{
    int h = blockIdx.y;
    int m0 = blockIdx.x * 128;
    int jmax = m0 + 128;

    float c[2][4][4];
    #pragma unroll
    for (int i = 0; i < 2; i++)
        #pragma unroll
        for (int j = 0; j < 4; j++)
            #pragma unroll
            for (int k = 0; k < 4; k++) c[i][j][k] = 0.f;

    mma3x_compute<0>(attn + (size_t)h * L * L, L, SV + (h >> 2) * HD, 256, m0, 0, jmax, c);

    __shared__ float wrs[16][64];
    __shared__ float Ss[128][17];
    int tid = threadIdx.x;
    for (int t = tid; t < 16 * 64; t += 256) {
        int rr = t >> 6, n = t & 63;
        wrs[rr][n] = wr[(size_t)rr * (NH * HD) + h * HD + n];
    }
    for (int t = tid; t < 128 * 16; t += 256) {
        int m = t >> 4, rr = t & 15;
        Ss[m][rr] = S[((size_t)(m0 + m) * NH + h) * NR + rr];
    }
    __syncthreads();

    int lane = tid & 31, warp = tid >> 5;
    int tq = lane >> 2, tr = lane & 3;
    int mb = (warp & 3) * 32, nb = (warp >> 2) * 32;
    #pragma unroll
    for (int rr = 0; rr < 16; rr++) {
        #pragma unroll
        for (int ma = 0; ma < 2; ma++) {
            float s0 = Ss[mb + ma * 16 + tq][rr];
            float s1 = Ss[mb + ma * 16 + tq + 8][rr];
            #pragma unroll
            for (int na = 0; na < 4; na++) {
                int col = nb + na * 8 + 2 * tr;
                float w0 = wrs[rr][col], w1 = wrs[rr][col + 1];
                c[ma][na][0] += s0 * w0; c[ma][na][1] += s0 * w1;
                c[ma][na][2] += s1 * w0; c[ma][na][3] += s1 * w1;
            }
        }
    }
    #pragma unroll
    for (int ma = 0; ma < 2; ma++) {
        int row = m0 + mb + ma * 16 + tq;
        #pragma unroll
        for (int na = 0; na < 4; na++) {
            int col = h * HD + nb + na * 8 + 2 * tr;
            *reinterpret_cast<float2*>(&ctx[(size_t)row * (NH * HD) + col]) =
                make_float2(c[ma][na][0], c[ma][na][1]);
            *reinterpret_cast<float2*>(&ctx[(size_t)(row + 8) * (NH * HD) + col]) =
                make_float2(c[ma][na][2], c[ma][na][3]);
        }
    }
}

// ---------------- causal softmax: 128 thr/row, register-resident -------------
__global__ void __launch_bounds__(128) softmax_kernel(float* __restrict__ attn) {
    int row = blockIdx.x;
    int i = row & (L - 1);
    int len = i + 1;
    float4* p4 = reinterpret_cast<float4*>(attn + (size_t)row * L);
    int tid = threadIdx.x;
    int lane = tid & 31, wid = tid >> 5;
    int base = tid * 4;

    float4 v = p4[tid];
    float e0 = (base + 0 < len) ? v.x : -3.0e38f;
    float e1 = (base + 1 < len) ? v.y : -3.0e38f;
    float e2 = (base + 2 < len) ? v.z : -3.0e38f;
    float e3 = (base + 3 < len) ? v.w : -3.0e38f;

    float m = fmaxf(fmaxf(e0, e1), fmaxf(e2, e3));
    #pragma unroll
    for (int off = 16; off > 0; off >>= 1)
        m = fmaxf(m, __shfl_xor_sync(0xFFFFFFFFu, m, off));

    __shared__ float sm[8];
    if (lane == 0) sm[wid] = m;
    __syncthreads();
    m = fmaxf(fmaxf(sm[0], sm[1]), fmaxf(sm[2], sm[3]));

    float x0 = (base + 0 < len) ? __expf(e0 - m) : 0.f;
    float x1 = (base + 1 < len) ? __expf(e1 - m) : 0.f;
    float x2 = (base + 2 < len) ? __expf(e2 - m) : 0.f;
    float x3 = (base + 3 < len) ? __expf(e3 - m) : 0.f;

    float s = x0 + x1 + x2 + x3;
    #pragma unroll
    for (int off = 16; off > 0; off >>= 1)
        s += __shfl_xor_sync(0xFFFFFFFFu, s, off);
    if (lane == 0) sm[4 + wid] = s;
    __syncthreads();
    float inv = 1.f / (sm[4] + sm[5] + sm[6] + sm[7]);

    p4[tid] = make_float4(x0 * inv, x1 * inv, x2 * inv, x3 * inv);
}

// ---------------- S[i,h,r] = sum_j attn[h,i,j] * rel[i,j,r] (staged) ---------
__global__ void __launch_bounds__(256) s_kernel(
    const float* __restrict__ attn, const float* __restrict__ rel,
    float* __restrict__ S)
{
    int i = blockIdx.x;
    int tid = threadIdx.x;
    int h = tid >> 4, r = tid & 15;
    __shared__ float attnS[16][128];
    __shared__ float relS[128][16];
    float acc = 0.f;
    int len = i + 1;
    for (int j0 = 0; j0 < len; j0 += 128) {
        // attn chunk: 16 h x 128 j (attn is zero beyond the diagonal)
        #pragma unroll
        for (int e = tid; e < 512; e += 256) {
            int hh = e >> 5, q = e & 31;
            *reinterpret_cast<float4*>(&attnS[hh][q * 4]) =
                *reinterpret_cast<const float4*>(&attn[((size_t)hh * L + i) * L + j0 + q * 4]);
        }
        // rel chunk: 128 j x 16 r
        #pragma unroll
        for (int e = tid; e < 512; e += 256) {
            int jj = e >> 2, q = e & 3;
            *reinterpret_cast<float4*>(&relS[jj][q * 4]) =
                *reinterpret_cast<const float4*>(&rel[((size_t)i * L + j0 + jj) * NR + q * 4]);
        }
        __syncthreads();
        #pragma unroll 16
        for (int jj = 0; jj < 128; jj++)
            acc += attnS[h][jj] * relS[jj][r];
        __syncthreads();
    }
    S[((size_t)i * NH + h) * NR + r] = acc;
}

// ---------------------------------------------------------------------------
extern "C" void kernel_launch(void* const* d_in, const int* in_sizes, int n_in,
                              void* d_out, int out_size) {
    const float* x       = (const float*)d_in[0];
    const float* symbols = (const float*)d_in[1];
    const float* fcos    = (const float*)d_in[2];
    const float* fsin    = (const float*)d_in[3];
    const float* wq_attn = (const float*)d_in[4];
    const float* wk_attn = (const float*)d_in[5];
    const float* wq_rel  = (const float*)d_in[6];
    const float* wk_rel  = (const float*)d_in[7];
    const float* wr      = (const float*)d_in[8];
    const float* wv      = (const float*)d_in[9];
    const float* wo      = (const float*)d_in[10];

    float* out  = (float*)d_out;
    float* attn = out + (size_t)L * NH * HD;
    float* rel  = attn + (size_t)NH * L * L;

    float *Q, *K, *QR, *KR, *SV, *S, *CTX;
    cudaGetSymbolAddress((void**)&Q,  g_Q);
    cudaGetSymbolAddress((void**)&K,  g_K);
    cudaGetSymbolAddress((void**)&QR, g_QR);
    cudaGetSymbolAddress((void**)&KR, g_KR);
    cudaGetSymbolAddress((void**)&SV, g_SV);
    cudaGetSymbolAddress((void**)&S,  g_S);
    cudaGetSymbolAddress((void**)&CTX, g_CTX);

    // 1) projections + fused RoPE
    proj_mma_kernel<<<dim3(4, 56), 256>>>(x, symbols, wq_attn, wq_rel, wk_rel,
                                          wk_attn, wv, fcos, fsin, Q, K, QR, KR, SV);

    // 2) scores (3xTF32) + softmax
    scores3x_kernel<<<dim3(8, 4, NH), 256>>>(Q, K, attn);
    softmax_kernel<<<NH * L, 128>>>(attn);

    // 3) relations (3xTF32)
    relations3x_kernel<<<dim3(8, 4, NR), 256>>>(QR, KR, rel);

    // 4) S factorization (staged)
    s_kernel<<<L, 256>>>(attn, rel, S);

    // 5) ctx = attn@sv (3xTF32) + S@wr
    attended3x_kernel<<<dim3(4, NH), 256>>>(attn, SV, S, wr, CTX);

    // 6) out = ctx @ wo
    out_mma_kernel<<<dim3(4, 16), 256>>>(CTX, wo, out);
}

// round 7
// speedup vs baseline: 5.0670x; 1.1622x over previous
#include <cuda_runtime.h>
#include <cuda_bf16.h>
#include <cstdint>
#include <math.h>

#define L 512
#define Dm 1024
#define NH 16
#define NKV 4
#define NR 16
#define HD 64
#define ATTN_SCALE 0.125f
#define REL_SCALE 0.125f

// ---------------- scratch ----------------------------------------------------
__device__ float g_Q[L * NH * HD];
__device__ float g_K[L * NKV * HD];
__device__ float g_QR[L * NR * HD];
__device__ float g_KR[L * NR * HD];
__device__ float g_SV[L * NKV * HD];
__device__ float g_S[L * NH * NR];
__device__ float g_CTX[L * NH * HD];
__device__ float g_RELT[NR * L * L];   // relations in [r][i][j] (coalesced compute layout)

__device__ __forceinline__ float to_tf32(float x) {
    uint32_t u;
    asm("cvt.rna.tf32.f32 %0, %1;" : "=r"(u) : "f"(x));
    return __uint_as_float(u);
}
__device__ __forceinline__ void mma_tf32(float c[4], uint32_t a0, uint32_t a1,
                                         uint32_t a2, uint32_t a3,
                                         uint32_t b0, uint32_t b1) {
    asm volatile(
        "mma.sync.aligned.m16n8k8.row.col.f32.tf32.tf32.f32 "
        "{%0,%1,%2,%3}, {%4,%5,%6,%7}, {%8,%9}, {%0,%1,%2,%3};"
        : "+f"(c[0]), "+f"(c[1]), "+f"(c[2]), "+f"(c[3])
        : "r"(a0), "r"(a1), "r"(a2), "r"(a3), "r"(b0), "r"(b1));
}

// ---------------- pipelined tf32 GEMM tile (projections / out) ---------------
__device__ __forceinline__ void mma_gemm_tile(
    const float* __restrict__ A, int lda,
    const float* __restrict__ W, int ldb,
    float* __restrict__ C, int ldc,
    int m0, int n0, int K,
    const float* __restrict__ fcos, const float* __restrict__ fsin, int ropef)
{
    __shared__ float As[128][36];
    __shared__ float Bs[32][72];

    int tid = threadIdx.x;
    int warp = tid >> 5, lane = tid & 31;
    int tq = lane >> 2, tr = lane & 3;
    int wm = warp & 3, wn = warp >> 2;
    int mb = wm * 32, nb = wn * 32;

    float c[2][4][4];
    #pragma unroll
    for (int i = 0; i < 2; i++)
        #pragma unroll
        for (int j = 0; j < 4; j++)
            #pragma unroll
            for (int k = 0; k < 4; k++) c[i][j][k] = 0.f;

    float4 pa[4], pb[2];
    #pragma unroll
    for (int i = 0; i < 4; i++) {
        int e = tid + i * 256;
        int r = e >> 3, c4 = e & 7;
        pa[i] = *reinterpret_cast<const float4*>(&A[(size_t)(m0 + r) * lda + c4 * 4]);
    }
    #pragma unroll
    for (int i = 0; i < 2; i++) {
        int e = tid + i * 256;
        int k = e >> 4, n4 = e & 15;
        pb[i] = *reinterpret_cast<const float4*>(&W[(size_t)k * ldb + n0 + n4 * 4]);
    }

    int nch = K >> 5;
    for (int kc = 0; kc < nch; kc++) {
        #pragma unroll
        for (int i = 0; i < 4; i++) {
            int e = tid + i * 256;
            int r = e >> 3, c4 = e & 7;
            float4 v = pa[i];
            v.x = to_tf32(v.x); v.y = to_tf32(v.y); v.z = to_tf32(v.z); v.w = to_tf32(v.w);
            *reinterpret_cast<float4*>(&As[r][c4 * 4]) = v;
        }
        #pragma unroll
        for (int i = 0; i < 2; i++) {
            int e = tid + i * 256;
            int k = e >> 4, n4 = e & 15;
            float4 v = pb[i];
            v.x = to_tf32(v.x); v.y = to_tf32(v.y); v.z = to_tf32(v.z); v.w = to_tf32(v.w);
            *reinterpret_cast<float4*>(&Bs[k][n4 * 4]) = v;
        }
        __syncthreads();
        if (kc + 1 < nch) {
            int k0n = (kc + 1) << 5;
            #pragma unroll
            for (int i = 0; i < 4; i++) {
                int e = tid + i * 256;
                int r = e >> 3, c4 = e & 7;
                pa[i] = *reinterpret_cast<const float4*>(&A[(size_t)(m0 + r) * lda + k0n + c4 * 4]);
            }
            #pragma unroll
            for (int i = 0; i < 2; i++) {
                int e = tid + i * 256;
                int k = e >> 4, n4 = e & 15;
                pb[i] = *reinterpret_cast<const float4*>(&W[(size_t)(k0n + k) * ldb + n0 + n4 * 4]);
            }
        }
        #pragma unroll
        for (int ks = 0; ks < 4; ks++) {
            int kb = ks * 8;
            uint32_t a[2][4], b[4][2];
            #pragma unroll
            for (int ma = 0; ma < 2; ma++) {
                int r0 = mb + ma * 16 + tq;
                a[ma][0] = __float_as_uint(As[r0][kb + tr]);
                a[ma][1] = __float_as_uint(As[r0 + 8][kb + tr]);
                a[ma][2] = __float_as_uint(As[r0][kb + tr + 4]);
                a[ma][3] = __float_as_uint(As[r0 + 8][kb + tr + 4]);
            }
            #pragma unroll
            for (int na = 0; na < 4; na++) {
                int n_ = nb + na * 8 + tq;
                b[na][0] = __float_as_uint(Bs[kb + tr][n_]);
                b[na][1] = __float_as_uint(Bs[kb + tr + 4][n_]);
            }
            #pragma unroll
            for (int ma = 0; ma < 2; ma++)
                #pragma unroll
                for (int na = 0; na < 4; na++)
                    mma_tf32(c[ma][na], a[ma][0], a[ma][1], a[ma][2], a[ma][3],
                             b[na][0], b[na][1]);
        }
        __syncthreads();
    }

    #pragma unroll
    for (int ma = 0; ma < 2; ma++) {
        int row = m0 + mb + ma * 16 + tq;
        #pragma unroll
        for (int na = 0; na < 4; na++) {
            int col = n0 + nb + na * 8 + 2 * tr;
            float v0 = c[ma][na][0], v1 = c[ma][na][1];
            float v2 = c[ma][na][2], v3 = c[ma][na][3];
            if (ropef) {
                int p = (col & 63) >> 1;
                float c0 = fcos[row * 32 + p], s0 = fsin[row * 32 + p];
                float c1 = fcos[(row + 8) * 32 + p], s1 = fsin[(row + 8) * 32 + p];
                float t0 = v0 * c0 - v1 * s0, t1 = v0 * s0 + v1 * c0;
                float t2 = v2 * c1 - v3 * s1, t3 = v2 * s1 + v3 * c1;
                v0 = t0; v1 = t1; v2 = t2; v3 = t3;
            }
            *reinterpret_cast<float2*>(&C[(size_t)row * ldc + col]) = make_float2(v0, v1);
            *reinterpret_cast<float2*>(&C[(size_t)(row + 8) * ldc + col]) = make_float2(v2, v3);
        }
    }
}

__global__ void __launch_bounds__(256, 2) proj_mma_kernel(
    const float* __restrict__ x, const float* __restrict__ symbols,
    const float* __restrict__ wq, const float* __restrict__ wqr,
    const float* __restrict__ wkr, const float* __restrict__ wk,
    const float* __restrict__ wv,
    const float* __restrict__ fcos, const float* __restrict__ fsin,
    float* __restrict__ Q, float* __restrict__ Kp, float* __restrict__ QR,
    float* __restrict__ KR, float* __restrict__ SV)
{
    int mt = blockIdx.x;
    int t = blockIdx.y;
    const float* A = x;
    const float* W;
    float* C;
    int ldb, n0, ropef = 0;
    if (t < 16)      { W = wq;  C = Q;  ldb = 1024; n0 = t * 64; ropef = 1; }
    else if (t < 32) { W = wqr; C = QR; ldb = 1024; n0 = (t - 16) * 64; }
    else if (t < 48) { W = wkr; C = KR; ldb = 1024; n0 = (t - 32) * 64; }
    else if (t < 52) { W = wk;  C = Kp; ldb = 256;  n0 = (t - 48) * 64; ropef = 1; }
    else             { W = wv; A = symbols; C = SV; ldb = 256; n0 = (t - 52) * 64; }
    mma_gemm_tile(A, 1024, W, ldb, C, ldb, mt * 128, n0, 1024, fcos, fsin, ropef);
}

__global__ void __launch_bounds__(256, 2) out_mma_kernel(
    const float* __restrict__ CTX, const float* __restrict__ wo, float* __restrict__ out)
{
    mma_gemm_tile(CTX, 1024, wo, 1024, out, 1024, blockIdx.x * 128, blockIdx.y * 64, 1024,
                  nullptr, nullptr, 0);
}

// ---------------- 3xTF32 compute core with register-prefetch pipeline --------
// BNK=1: B stored [n][k] rows at n0.  BNK=0: B stored [k][n], cols at n0.
template<int BNK>
__device__ __forceinline__ void mma3x_compute(
    const float* __restrict__ A, int lda,
    const float* __restrict__ B, int ldb,
    int m0, int n0, int kmax, float c[2][4][4])
{
    constexpr int BR = BNK ? 64 : 16;
    constexpr int BC = BNK ? 20 : 72;
    __shared__ float As_hi[128][20], As_lo[128][20];
    __shared__ float Bs_hi[BR][BC], Bs_lo[BR][BC];

    int tid = threadIdx.x;
    int warp = tid >> 5, lane = tid & 31;
    int tq = lane >> 2, tr = lane & 3;
    int wm = warp & 3, wn = warp >> 2;
    int mb = wm * 32, nb = wn * 32;

    float4 pa[2], pb;
    #pragma unroll
    for (int i = 0; i < 2; i++) {
        int e = tid + i * 256;
        int r = e >> 2, k4 = e & 3;
        pa[i] = *reinterpret_cast<const float4*>(&A[(size_t)(m0 + r) * lda + k4 * 4]);
    }
    if (BNK) {
        int r = tid >> 2, k4 = tid & 3;
        pb = *reinterpret_cast<const float4*>(&B[(size_t)(n0 + r) * ldb + k4 * 4]);
    } else {
        int k = tid >> 4, n4 = tid & 15;
        pb = *reinterpret_cast<const float4*>(&B[(size_t)k * ldb + n0 + n4 * 4]);
    }

    for (int k0 = 0; k0 < kmax; k0 += 16) {
        #pragma unroll
        for (int i = 0; i < 2; i++) {
            int e = tid + i * 256;
            int r = e >> 2, k4 = e & 3;
            float4 v = pa[i];
            float4 h = make_float4(to_tf32(v.x), to_tf32(v.y), to_tf32(v.z), to_tf32(v.w));
            float4 l = make_float4(to_tf32(v.x - h.x), to_tf32(v.y - h.y),
                                   to_tf32(v.z - h.z), to_tf32(v.w - h.w));
            *reinterpret_cast<float4*>(&As_hi[r][k4 * 4]) = h;
            *reinterpret_cast<float4*>(&As_lo[r][k4 * 4]) = l;
        }
        {
            float4 v = pb;
            float4 h = make_float4(to_tf32(v.x), to_tf32(v.y), to_tf32(v.z), to_tf32(v.w));
            float4 l = make_float4(to_tf32(v.x - h.x), to_tf32(v.y - h.y),
                                   to_tf32(v.z - h.z), to_tf32(v.w - h.w));
            if (BNK) {
                int r = tid >> 2, k4 = tid & 3;
                *reinterpret_cast<float4*>(&Bs_hi[r][k4 * 4]) = h;
                *reinterpret_cast<float4*>(&Bs_lo[r][k4 * 4]) = l;
            } else {
                int k = tid >> 4, n4 = tid & 15;
                *reinterpret_cast<float4*>(&Bs_hi[k][n4 * 4]) = h;
                *reinterpret_cast<float4*>(&Bs_lo[k][n4 * 4]) = l;
            }
        }
        __syncthreads();
        if (k0 + 16 < kmax) {
            int kn = k0 + 16;
            #pragma unroll
            for (int i = 0; i < 2; i++) {
                int e = tid + i * 256;
                int r = e >> 2, k4 = e & 3;
                pa[i] = *reinterpret_cast<const float4*>(&A[(size_t)(m0 + r) * lda + kn + k4 * 4]);
            }
            if (BNK) {
                int r = tid >> 2, k4 = tid & 3;
                pb = *reinterpret_cast<const float4*>(&B[(size_t)(n0 + r) * ldb + kn + k4 * 4]);
            } else {
                int k = tid >> 4, n4 = tid & 15;
                pb = *reinterpret_cast<const float4*>(&B[(size_t)(kn + k) * ldb + n0 + n4 * 4]);
            }
        }
        #pragma unroll
        for (int ks = 0; ks < 2; ks++) {
            int kb = ks * 8;
            uint32_t ah[2][4], al[2][4], bh[4][2], bl[4][2];
            #pragma unroll
            for (int ma = 0; ma < 2; ma++) {
                int r0 = mb + ma * 16 + tq;
                ah[ma][0] = __float_as_uint(As_hi[r0][kb + tr]);
                ah[ma][1] = __float_as_uint(As_hi[r0 + 8][kb + tr]);
                ah[ma][2] = __float_as_uint(As_hi[r0][kb + tr + 4]);
                ah[ma][3] = __float_as_uint(As_hi[r0 + 8][kb + tr + 4]);
                al[ma][0] = __float_as_uint(As_lo[r0][kb + tr]);
                al[ma][1] = __float_as_uint(As_lo[r0 + 8][kb + tr]);
                al[ma][2] = __float_as_uint(As_lo[r0][kb + tr + 4]);
                al[ma][3] = __float_as_uint(As_lo[r0 + 8][kb + tr + 4]);
            }
            #pragma unroll
            for (int na = 0; na < 4; na++) {
                int n_ = nb + na * 8 + tq;
                if (BNK) {
                    bh[na][0] = __float_as_uint(Bs_hi[n_][kb + tr]);
                    bh[na][1] = __float_as_uint(Bs_hi[n_][kb + tr + 4]);
                    bl[na][0] = __float_as_uint(Bs_lo[n_][kb + tr]);
                    bl[na][1] = __float_as_uint(Bs_lo[n_][kb + tr + 4]);
                } else {
                    bh[na][0] = __float_as_uint(Bs_hi[kb + tr][n_]);
                    bh[na][1] = __float_as_uint(Bs_hi[kb + tr + 4][n_]);
                    bl[na][0] = __float_as_uint(Bs_lo[kb + tr][n_]);
                    bl[na][1] = __float_as_uint(Bs_lo[kb + tr + 4][n_]);
                }
            }
            #pragma unroll
            for (int ma = 0; ma < 2; ma++)
                #pragma unroll
                for (int na = 0; na < 4; na++) {
                    mma_tf32(c[ma][na], ah[ma][0], ah[ma][1], ah[ma][2], ah[ma][3],
                             bl[na][0], bl[na][1]);
                    mma_tf32(c[ma][na], al[ma][0], al[ma][1], al[ma][2], al[ma][3],
                             bh[na][0], bh[na][1]);
                    mma_tf32(c[ma][na], ah[ma][0], ah[ma][1], ah[ma][2], ah[ma][3],
                             bh[na][0], bh[na][1]);
                }
        }
        __syncthreads();
    }
}

// ---------------- scores (3xTF32) --------------------------------------------
__global__ void __launch_bounds__(256, 2) scores3x_kernel(
    const float* __restrict__ Q, const float* __restrict__ K, float* __restrict__ attn)
{
    int h = blockIdx.z;
    int m0 = blockIdx.y * 128, n0 = blockIdx.x * 64;
    if (n0 >= m0 + 128) return;

    float c[2][4][4];
    #pragma unroll
    for (int i = 0; i < 2; i++)
        #pragma unroll
        for (int j = 0; j < 4; j++)
            #pragma unroll
            for (int k = 0; k < 4; k++) c[i][j][k] = 0.f;

    mma3x_compute<1>(Q + h * HD, 1024, K + (h >> 2) * HD, 256, m0, n0, 64, c);

    int lane = threadIdx.x & 31, warp = threadIdx.x >> 5;
    int tq = lane >> 2, tr = lane & 3;
    int mb = (warp & 3) * 32, nb = (warp >> 2) * 32;
    float* C = attn + (size_t)h * L * L;
    #pragma unroll
    for (int ma = 0; ma < 2; ma++) {
        int row = m0 + mb + ma * 16 + tq;
        #pragma unroll
        for (int na = 0; na < 4; na++) {
            int col = n0 + nb + na * 8 + 2 * tr;
            *reinterpret_cast<float2*>(&C[(size_t)row * L + col]) =
                make_float2(c[ma][na][0] * ATTN_SCALE, c[ma][na][1] * ATTN_SCALE);
            *reinterpret_cast<float2*>(&C[(size_t)(row + 8) * L + col]) =
                make_float2(c[ma][na][2] * ATTN_SCALE, c[ma][na][3] * ATTN_SCALE);
        }
    }
}

// ---------------- relations (3xTF32) -> relT[r][i][j] coalesced --------------
__global__ void __launch_bounds__(256, 2) relations3x_kernel(
    const float* __restrict__ QR, const float* __restrict__ KR, float* __restrict__ relT)
{
    int r = blockIdx.z;
    int m0 = blockIdx.y * 128, n0 = blockIdx.x * 64;

    float c[2][4][4];
    #pragma unroll
    for (int i = 0; i < 2; i++)
        #pragma unroll
        for (int j = 0; j < 4; j++)
            #pragma unroll
            for (int k = 0; k < 4; k++) c[i][j][k] = 0.f;

    mma3x_compute<1>(QR + r * HD, 1024, KR + r * HD, 1024, m0, n0, 64, c);

    int lane = threadIdx.x & 31, warp = threadIdx.x >> 5;
    int tq = lane >> 2, tr = lane & 3;
    int mb = (warp & 3) * 32, nb = (warp >> 2) * 32;
    float* C = relT + (size_t)r * L * L;
    #pragma unroll
    for (int ma = 0; ma < 2; ma++) {
        int row = m0 + mb + ma * 16 + tq;
        #pragma unroll
        for (int na = 0; na < 4; na++) {
            int col = n0 + nb + na * 8 + 2 * tr;
            *reinterpret_cast<float2*>(&C[(size_t)row * L + col]) =
                make_float2(c[ma][na][0] * REL_SCALE, c[ma][na][1] * REL_SCALE);
            *reinterpret_cast<float2*>(&C[(size_t)(row + 8) * L + col]) =
                make_float2(c[ma][na][2] * REL_SCALE, c[ma][na][3] * REL_SCALE);
        }
    }
}

// ---------------- relT[r][i][j] -> rel[i][j][r] (both sides coalesced) -------
__global__ void __launch_bounds__(128) reltrans_kernel(
    const float* __restrict__ relT, float* __restrict__ rel)
{
    int i = blockIdx.y;
    int j0 = blockIdx.x * 128;
    int tid = threadIdx.x;
    __shared__ float t[16][132];
    // load: 16 r rows x 128 j, coalesced float4
    #pragma unroll
    for (int e = tid; e < 512; e += 128) {
        int rr = e >> 5, q = e & 31;
        *reinterpret_cast<float4*>(&t[rr][q * 4]) =
            *reinterpret_cast<const float4*>(&relT[((size_t)rr * L + i) * L + j0 + q * 4]);
    }
    __syncthreads();
    // store: each thread covers (j, 4r): consecutive threads fill full 64B r-vectors
    #pragma unroll
    for (int e = tid; e < 512; e += 128) {
        int j = e >> 2, rq = e & 3;
        float4 v = make_float4(t[rq * 4 + 0][j], t[rq * 4 + 1][j],
                               t[rq * 4 + 2][j], t[rq * 4 + 3][j]);
        *reinterpret_cast<float4*>(&rel[((size_t)i * L + j0 + j) * NR + rq * 4]) = v;
    }
}

// ---------------- attended (3xTF32 attn@sv + S@wr) ---------------------------
__global__ void __launch_bounds__(256, 2) attended3x_kernel(
    const float* __restrict__ attn, const float* __restrict__ SV,
    const float* __restrict__ S, const float* __restrict__ wr,
    float* __restrict__ ctx)
{
    int h = blockIdx.y;
    int m0 = blockIdx.x * 128;
    int jmax = m0 + 128;

    float c[2][4][4];
    #pragma unroll
    for (int i = 0; i < 2; i++)
        #pragma unroll
        for (int j = 0; j < 4; j++)
            #pragma unroll
            for (int k = 0; k < 4; k++) c[i][j][k] = 0.f;

    mma3x_compute<0>(attn + (size_t)h * L * L, L, SV + (h >> 2) * HD, 256, m0, 0, jmax, c);

    __shared__ float wrs[16][64];
    __shared__ float Ss[128][17];
    int tid = threadIdx.x;
    for (int t = tid; t < 16 * 64; t += 256) {
        int rr = t >> 6, n = t & 63;
        wrs[rr][n] = wr[(size_t)rr * (NH * HD) + h * HD + n];
    }
    for (int t = tid; t < 128 * 16; t += 256) {
        int m = t >> 4, rr = t & 15;
        Ss[m][rr] = S[((size_t)(m0 + m) * NH + h) * NR + rr];
    }
    __syncthreads();

    int lane = tid & 31, warp = tid >> 5;
    int tq = lane >> 2, tr = lane & 3;
    int mb = (warp & 3) * 32, nb = (warp >> 2) * 32;
    #pragma unroll
    for (int rr = 0; rr < 16; rr++) {
        #pragma unroll
        for (int ma = 0; ma < 2; ma++) {
            float s0 = Ss[mb + ma * 16 + tq][rr];
            float s1 = Ss[mb + ma * 16 + tq + 8][rr];
            #pragma unroll
            for (int na = 0; na < 4; na++) {
                int col = nb + na * 8 + 2 * tr;
                float w0 = wrs[rr][col], w1 = wrs[rr][col + 1];
                c[ma][na][0] += s0 * w0; c[ma][na][1] += s0 * w1;
                c[ma][na][2] += s1 * w0; c[ma][na][3] += s1 * w1;
            }
        }
    }
    #pragma unroll
    for (int ma = 0; ma < 2; ma++) {
        int row = m0 + mb + ma * 16 + tq;
        #pragma unroll
        for (int na = 0; na < 4; na++) {
            int col = h * HD + nb + na * 8 + 2 * tr;
            *reinterpret_cast<float2*>(&ctx[(size_t)row * (NH * HD) + col]) =
                make_float2(c[ma][na][0], c[ma][na][1]);
            *reinterpret_cast<float2*>(&ctx[(size_t)(row + 8) * (NH * HD) + col]) =
                make_float2(c[ma][na][2], c[ma][na][3]);
        }
    }
}

// ---------------- causal softmax ---------------------------------------------
__global__ void __launch_bounds__(128) softmax_kernel(float* __restrict__ attn) {
    int row = blockIdx.x;
    int i = row & (L - 1);
    int len = i + 1;
    float4* p4 = reinterpret_cast<float4*>(attn + (size_t)row * L);
    int tid = threadIdx.x;
    int lane = tid & 31, wid = tid >> 5;
    int base = tid * 4;

    float4 v = p4[tid];
    float e0 = (base + 0 < len) ? v.x : -3.0e38f;
    float e1 = (base + 1 < len) ? v.y : -3.0e38f;
    float e2 = (base + 2 < len) ? v.z : -3.0e38f;
    float e3 = (base + 3 < len) ? v.w : -3.0e38f;

    float m = fmaxf(fmaxf(e0, e1), fmaxf(e2, e3));
    #pragma unroll
    for (int off = 16; off > 0; off >>= 1)
        m = fmaxf(m, __shfl_xor_sync(0xFFFFFFFFu, m, off));

    __shared__ float sm[8];
    if (lane == 0) sm[wid] = m;
    __syncthreads();
    m = fmaxf(fmaxf(sm[0], sm[1]), fmaxf(sm[2], sm[3]));

    float x0 = (base + 0 < len) ? __expf(e0 - m) : 0.f;
    float x1 = (base + 1 < len) ? __expf(e1 - m) : 0.f;
    float x2 = (base + 2 < len) ? __expf(e2 - m) : 0.f;
    float x3 = (base + 3 < len) ? __expf(e3 - m) : 0.f;

    float s = x0 + x1 + x2 + x3;
    #pragma unroll
    for (int off = 16; off > 0; off >>= 1)
        s += __shfl_xor_sync(0xFFFFFFFFu, s, off);
    if (lane == 0) sm[4 + wid] = s;
    __syncthreads();
    float inv = 1.f / (sm[4] + sm[5] + sm[6] + sm[7]);

    p4[tid] = make_float4(x0 * inv, x1 * inv, x2 * inv, x3 * inv);
}

// ---------------- S[i,h,r] = sum_j attn[h,i,j] * relT[r,i,j] -----------------
__global__ void __launch_bounds__(256) s_kernel(
    const float* __restrict__ attn, const float* __restrict__ relT,
    float* __restrict__ S)
{
    int i = blockIdx.x;
    int tid = threadIdx.x;
    int h = tid >> 4, r = tid & 15;
    __shared__ float attnS[16][132];
    __shared__ float relS[16][132];
    float acc = 0.f;
    int len = i + 1;
    for (int j0 = 0; j0 < len; j0 += 128) {
        #pragma unroll
        for (int e = tid; e < 512; e += 256) {
            int hh = e >> 5, q = e & 31;
            *reinterpret_cast<float4*>(&attnS[hh][q * 4]) =
                *reinterpret_cast<const float4*>(&attn[((size_t)hh * L + i) * L + j0 + q * 4]);
        }
        #pragma unroll
        for (int e = tid; e < 512; e += 256) {
            int rr = e >> 5, q = e & 31;
            *reinterpret_cast<float4*>(&relS[rr][q * 4]) =
                *reinterpret_cast<const float4*>(&relT[((size_t)rr * L + i) * L + j0 + q * 4]);
        }
        __syncthreads();
        #pragma unroll 16
        for (int jj = 0; jj < 128; jj++)
            acc += attnS[h][jj] * relS[r][jj];
        __syncthreads();
    }
    S[((size_t)i * NH + h) * NR + r] = acc;
}

// ---------------------------------------------------------------------------
extern "C" void kernel_launch(void* const* d_in, const int* in_sizes, int n_in,
                              void* d_out, int out_size) {
    const float* x       = (const float*)d_in[0];
    const float* symbols = (const float*)d_in[1];
    const float* fcos    = (const float*)d_in[2];
    const float* fsin    = (const float*)d_in[3];
    const float* wq_attn = (const float*)d_in[4];
    const float* wk_attn = (const float*)d_in[5];
    const float* wq_rel  = (const float*)d_in[6];
    const float* wk_rel  = (const float*)d_in[7];
    const float* wr      = (const float*)d_in[8];
    const float* wv      = (const float*)d_in[9];
    const float* wo      = (const float*)d_in[10];

    float* out  = (float*)d_out;
    float* attn = out + (size_t)L * NH * HD;
    float* rel  = attn + (size_t)NH * L * L;

    float *Q, *K, *QR, *KR, *SV, *S, *CTX, *RELT;
    cudaGetSymbolAddress((void**)&Q,  g_Q);
    cudaGetSymbolAddress((void**)&K,  g_K);
    cudaGetSymbolAddress((void**)&QR, g_QR);
    cudaGetSymbolAddress((void**)&KR, g_KR);
    cudaGetSymbolAddress((void**)&SV, g_SV);
    cudaGetSymbolAddress((void**)&S,  g_S);
    cudaGetSymbolAddress((void**)&CTX, g_CTX);
    cudaGetSymbolAddress((void**)&RELT, g_RELT);

    // 1) projections + fused RoPE
    proj_mma_kernel<<<dim3(4, 56), 256>>>(x, symbols, wq_attn, wq_rel, wk_rel,
                                          wk_attn, wv, fcos, fsin, Q, K, QR, KR, SV);

    // 2) scores (3xTF32) + softmax
    scores3x_kernel<<<dim3(8, 4, NH), 256>>>(Q, K, attn);
    softmax_kernel<<<NH * L, 128>>>(attn);

    // 3) relations (3xTF32) -> relT[r][i][j], then layout pass -> rel[i][j][r]
    relations3x_kernel<<<dim3(8, 4, NR), 256>>>(QR, KR, RELT);
    reltrans_kernel<<<dim3(4, L), 128>>>(RELT, rel);

    // 4) S factorization (reads coalesced relT)
    s_kernel<<<L, 256>>>(attn, RELT, S);

    // 5) ctx = attn@sv (3xTF32) + S@wr
    attended3x_kernel<<<dim3(4, NH), 256>>>(attn, SV, S, wr, CTX);

    // 6) out = ctx @ wo
    out_mma_kernel<<<dim3(4, 16), 256>>>(CTX, wo, out);
}

// round 8
// speedup vs baseline: 5.1179x; 1.0101x over previous
#include <cuda_runtime.h>
#include <cuda_bf16.h>
#include <cstdint>
#include <math.h>

#define L 512
#define Dm 1024
#define NH 16
#define NKV 4
#define NR 16
#define HD 64
#define ATTN_SCALE 0.125f
#define REL_SCALE 0.125f

// ---------------- scratch ----------------------------------------------------
__device__ float g_Q[L * NH * HD];
__device__ float g_K[L * NKV * HD];
__device__ float g_QR[L * NR * HD];
__device__ float g_KR[L * NR * HD];
__device__ float g_SV[L * NKV * HD];
__device__ float g_S[L * NH * NR];
__device__ float g_CTX[L * NH * HD];
__device__ float g_RELT[NR * L * L];   // relations in [r][i][j]

__device__ __forceinline__ float to_tf32(float x) {
    uint32_t u;
    asm("cvt.rna.tf32.f32 %0, %1;" : "=r"(u) : "f"(x));
    return __uint_as_float(u);
}
__device__ __forceinline__ void mma_tf32(float c[4], uint32_t a0, uint32_t a1,
                                         uint32_t a2, uint32_t a3,
                                         uint32_t b0, uint32_t b1) {
    asm volatile(
        "mma.sync.aligned.m16n8k8.row.col.f32.tf32.tf32.f32 "
        "{%0,%1,%2,%3}, {%4,%5,%6,%7}, {%8,%9}, {%0,%1,%2,%3};"
        : "+f"(c[0]), "+f"(c[1]), "+f"(c[2]), "+f"(c[3])
        : "r"(a0), "r"(a1), "r"(a2), "r"(a3), "r"(b0), "r"(b1));
}
__device__ __forceinline__ float2 hl_split(float x) {
    float h = to_tf32(x);
    return make_float2(h, to_tf32(x - h));
}

// ---------------- pipelined tf32 GEMM tile (projections / out) ---------------
__device__ __forceinline__ void mma_gemm_tile(
    const float* __restrict__ A, int lda,
    const float* __restrict__ W, int ldb,
    float* __restrict__ C, int ldc,
    int m0, int n0, int K,
    const float* __restrict__ fcos, const float* __restrict__ fsin, int ropef)
{
    __shared__ float As[128][36];
    __shared__ float Bs[32][72];

    int tid = threadIdx.x;
    int warp = tid >> 5, lane = tid & 31;
    int tq = lane >> 2, tr = lane & 3;
    int wm = warp & 3, wn = warp >> 2;
    int mb = wm * 32, nb = wn * 32;

    float c[2][4][4];
    #pragma unroll
    for (int i = 0; i < 2; i++)
        #pragma unroll
        for (int j = 0; j < 4; j++)
            #pragma unroll
            for (int k = 0; k < 4; k++) c[i][j][k] = 0.f;

    float4 pa[4], pb[2];
    #pragma unroll
    for (int i = 0; i < 4; i++) {
        int e = tid + i * 256;
        int r = e >> 3, c4 = e & 7;
        pa[i] = *reinterpret_cast<const float4*>(&A[(size_t)(m0 + r) * lda + c4 * 4]);
    }
    #pragma unroll
    for (int i = 0; i < 2; i++) {
        int e = tid + i * 256;
        int k = e >> 4, n4 = e & 15;
        pb[i] = *reinterpret_cast<const float4*>(&W[(size_t)k * ldb + n0 + n4 * 4]);
    }

    int nch = K >> 5;
    for (int kc = 0; kc < nch; kc++) {
        #pragma unroll
        for (int i = 0; i < 4; i++) {
            int e = tid + i * 256;
            int r = e >> 3, c4 = e & 7;
            float4 v = pa[i];
            v.x = to_tf32(v.x); v.y = to_tf32(v.y); v.z = to_tf32(v.z); v.w = to_tf32(v.w);
            *reinterpret_cast<float4*>(&As[r][c4 * 4]) = v;
        }
        #pragma unroll
        for (int i = 0; i < 2; i++) {
            int e = tid + i * 256;
            int k = e >> 4, n4 = e & 15;
            float4 v = pb[i];
            v.x = to_tf32(v.x); v.y = to_tf32(v.y); v.z = to_tf32(v.z); v.w = to_tf32(v.w);
            *reinterpret_cast<float4*>(&Bs[k][n4 * 4]) = v;
        }
        __syncthreads();
        if (kc + 1 < nch) {
            int k0n = (kc + 1) << 5;
            #pragma unroll
            for (int i = 0; i < 4; i++) {
                int e = tid + i * 256;
                int r = e >> 3, c4 = e & 7;
                pa[i] = *reinterpret_cast<const float4*>(&A[(size_t)(m0 + r) * lda + k0n + c4 * 4]);
            }
            #pragma unroll
            for (int i = 0; i < 2; i++) {
                int e = tid + i * 256;
                int k = e >> 4, n4 = e & 15;
                pb[i] = *reinterpret_cast<const float4*>(&W[(size_t)(k0n + k) * ldb + n0 + n4 * 4]);
            }
        }
        #pragma unroll
        for (int ks = 0; ks < 4; ks++) {
            int kb = ks * 8;
            uint32_t a[2][4], b[4][2];
            #pragma unroll
            for (int ma = 0; ma < 2; ma++) {
                int r0 = mb + ma * 16 + tq;
                a[ma][0] = __float_as_uint(As[r0][kb + tr]);
                a[ma][1] = __float_as_uint(As[r0 + 8][kb + tr]);
                a[ma][2] = __float_as_uint(As[r0][kb + tr + 4]);
                a[ma][3] = __float_as_uint(As[r0 + 8][kb + tr + 4]);
            }
            #pragma unroll
            for (int na = 0; na < 4; na++) {
                int n_ = nb + na * 8 + tq;
                b[na][0] = __float_as_uint(Bs[kb + tr][n_]);
                b[na][1] = __float_as_uint(Bs[kb + tr + 4][n_]);
            }
            #pragma unroll
            for (int ma = 0; ma < 2; ma++)
                #pragma unroll
                for (int na = 0; na < 4; na++)
                    mma_tf32(c[ma][na], a[ma][0], a[ma][1], a[ma][2], a[ma][3],
                             b[na][0], b[na][1]);
        }
        __syncthreads();
    }

    #pragma unroll
    for (int ma = 0; ma < 2; ma++) {
        int row = m0 + mb + ma * 16 + tq;
        #pragma unroll
        for (int na = 0; na < 4; na++) {
            int col = n0 + nb + na * 8 + 2 * tr;
            float v0 = c[ma][na][0], v1 = c[ma][na][1];
            float v2 = c[ma][na][2], v3 = c[ma][na][3];
            if (ropef) {
                int p = (col & 63) >> 1;
                float c0 = fcos[row * 32 + p], s0 = fsin[row * 32 + p];
                float c1 = fcos[(row + 8) * 32 + p], s1 = fsin[(row + 8) * 32 + p];
                float t0 = v0 * c0 - v1 * s0, t1 = v0 * s0 + v1 * c0;
                float t2 = v2 * c1 - v3 * s1, t3 = v2 * s1 + v3 * c1;
                v0 = t0; v1 = t1; v2 = t2; v3 = t3;
            }
            *reinterpret_cast<float2*>(&C[(size_t)row * ldc + col]) = make_float2(v0, v1);
            *reinterpret_cast<float2*>(&C[(size_t)(row + 8) * ldc + col]) = make_float2(v2, v3);
        }
    }
}

__global__ void __launch_bounds__(256, 2) proj_mma_kernel(
    const float* __restrict__ x, const float* __restrict__ symbols,
    const float* __restrict__ wq, const float* __restrict__ wqr,
    const float* __restrict__ wkr, const float* __restrict__ wk,
    const float* __restrict__ wv,
    const float* __restrict__ fcos, const float* __restrict__ fsin,
    float* __restrict__ Q, float* __restrict__ Kp, float* __restrict__ QR,
    float* __restrict__ KR, float* __restrict__ SV)
{
    int mt = blockIdx.x;
    int t = blockIdx.y;
    const float* A = x;
    const float* W;
    float* C;
    int ldb, n0, ropef = 0;
    if (t < 16)      { W = wq;  C = Q;  ldb = 1024; n0 = t * 64; ropef = 1; }
    else if (t < 32) { W = wqr; C = QR; ldb = 1024; n0 = (t - 16) * 64; }
    else if (t < 48) { W = wkr; C = KR; ldb = 1024; n0 = (t - 32) * 64; }
    else if (t < 52) { W = wk;  C = Kp; ldb = 256;  n0 = (t - 48) * 64; ropef = 1; }
    else             { W = wv; A = symbols; C = SV; ldb = 256; n0 = (t - 52) * 64; }
    mma_gemm_tile(A, 1024, W, ldb, C, ldb, mt * 128, n0, 1024, fcos, fsin, ropef);
}

__global__ void __launch_bounds__(256, 2) out_mma_kernel(
    const float* __restrict__ CTX, const float* __restrict__ wo, float* __restrict__ out)
{
    mma_gemm_tile(CTX, 1024, wo, 1024, out, 1024, blockIdx.x * 128, blockIdx.y * 64, 1024,
                  nullptr, nullptr, 0);
}

// ---------------- 3xTF32 core: (hi,lo) packed float2 smem, pipelined ---------
// BNK=1: B stored [n][k] rows at n0.  BNK=0: B stored [k][n], cols at n0.
template<int BNK>
__device__ __forceinline__ void mma3x_compute(
    const float* __restrict__ A, int lda,
    const float* __restrict__ B, int ldb,
    int m0, int n0, int kmax, float c[2][4][4])
{
    __shared__ float2 As[128][20];                    // (hi,lo) per (r,k)
    __shared__ float2 Bs[BNK ? 64 : 16][BNK ? 20 : 68];

    int tid = threadIdx.x;
    int warp = tid >> 5, lane = tid & 31;
    int tq = lane >> 2, tr = lane & 3;
    int wm = warp & 3, wn = warp >> 2;
    int mb = wm * 32, nb = wn * 32;

    float4 pa[2], pb;
    #pragma unroll
    for (int i = 0; i < 2; i++) {
        int e = tid + i * 256;
        int r = e >> 2, k4 = e & 3;
        pa[i] = *reinterpret_cast<const float4*>(&A[(size_t)(m0 + r) * lda + k4 * 4]);
    }
    if (BNK) {
        int r = tid >> 2, k4 = tid & 3;
        pb = *reinterpret_cast<const float4*>(&B[(size_t)(n0 + r) * ldb + k4 * 4]);
    } else {
        int k = tid >> 4, n4 = tid & 15;
        pb = *reinterpret_cast<const float4*>(&B[(size_t)k * ldb + n0 + n4 * 4]);
    }

    for (int k0 = 0; k0 < kmax; k0 += 16) {
        #pragma unroll
        for (int i = 0; i < 2; i++) {
            int e = tid + i * 256;
            int r = e >> 2, k4 = e & 3;
            float2 h0 = hl_split(pa[i].x), h1 = hl_split(pa[i].y);
            float2 h2 = hl_split(pa[i].z), h3 = hl_split(pa[i].w);
            *reinterpret_cast<float4*>(&As[r][k4 * 4]) =
                make_float4(h0.x, h0.y, h1.x, h1.y);
            *reinterpret_cast<float4*>(&As[r][k4 * 4 + 2]) =
                make_float4(h2.x, h2.y, h3.x, h3.y);
        }
        {
            float2 h0 = hl_split(pb.x), h1 = hl_split(pb.y);
            float2 h2 = hl_split(pb.z), h3 = hl_split(pb.w);
            if (BNK) {
                int r = tid >> 2, k4 = tid & 3;
                *reinterpret_cast<float4*>(&Bs[r][k4 * 4]) =
                    make_float4(h0.x, h0.y, h1.x, h1.y);
                *reinterpret_cast<float4*>(&Bs[r][k4 * 4 + 2]) =
                    make_float4(h2.x, h2.y, h3.x, h3.y);
            } else {
                int k = tid >> 4, n4 = tid & 15;
                *reinterpret_cast<float4*>(&Bs[k][n4 * 4]) =
                    make_float4(h0.x, h0.y, h1.x, h1.y);
                *reinterpret_cast<float4*>(&Bs[k][n4 * 4 + 2]) =
                    make_float4(h2.x, h2.y, h3.x, h3.y);
            }
        }
        __syncthreads();
        if (k0 + 16 < kmax) {
            int kn = k0 + 16;
            #pragma unroll
            for (int i = 0; i < 2; i++) {
                int e = tid + i * 256;
                int r = e >> 2, k4 = e & 3;
                pa[i] = *reinterpret_cast<const float4*>(&A[(size_t)(m0 + r) * lda + kn + k4 * 4]);
            }
            if (BNK) {
                int r = tid >> 2, k4 = tid & 3;
                pb = *reinterpret_cast<const float4*>(&B[(size_t)(n0 + r) * ldb + kn + k4 * 4]);
            } else {
                int k = tid >> 4, n4 = tid & 15;
                pb = *reinterpret_cast<const float4*>(&B[(size_t)(kn + k) * ldb + n0 + n4 * 4]);
            }
        }
        #pragma unroll
        for (int ks = 0; ks < 2; ks++) {
            int kb = ks * 8;
            float2 a0[2][4], b0[4][2];
            #pragma unroll
            for (int ma = 0; ma < 2; ma++) {
                int r0 = mb + ma * 16 + tq;
                a0[ma][0] = As[r0][kb + tr];
                a0[ma][1] = As[r0 + 8][kb + tr];
                a0[ma][2] = As[r0][kb + tr + 4];
                a0[ma][3] = As[r0 + 8][kb + tr + 4];
            }
            #pragma unroll
            for (int na = 0; na < 4; na++) {
                int n_ = nb + na * 8 + tq;
                if (BNK) {
                    b0[na][0] = Bs[n_][kb + tr];
                    b0[na][1] = Bs[n_][kb + tr + 4];
                } else {
                    b0[na][0] = Bs[kb + tr][n_];
                    b0[na][1] = Bs[kb + tr + 4][n_];
                }
            }
            #pragma unroll
            for (int ma = 0; ma < 2; ma++)
                #pragma unroll
                for (int na = 0; na < 4; na++) {
                    uint32_t ah0 = __float_as_uint(a0[ma][0].x), al0 = __float_as_uint(a0[ma][0].y);
                    uint32_t ah1 = __float_as_uint(a0[ma][1].x), al1 = __float_as_uint(a0[ma][1].y);
                    uint32_t ah2 = __float_as_uint(a0[ma][2].x), al2 = __float_as_uint(a0[ma][2].y);
                    uint32_t ah3 = __float_as_uint(a0[ma][3].x), al3 = __float_as_uint(a0[ma][3].y);
                    uint32_t bh0 = __float_as_uint(b0[na][0].x), bl0 = __float_as_uint(b0[na][0].y);
                    uint32_t bh1 = __float_as_uint(b0[na][1].x), bl1 = __float_as_uint(b0[na][1].y);
                    mma_tf32(c[ma][na], ah0, ah1, ah2, ah3, bl0, bl1);
                    mma_tf32(c[ma][na], al0, al1, al2, al3, bh0, bh1);
                    mma_tf32(c[ma][na], ah0, ah1, ah2, ah3, bh0, bh1);
                }
        }
        __syncthreads();
    }
}

// ---------------- fused scores + relations (3xTF32) --------------------------
// z < 16: scores head h=z (causal skip). z >= 16: relations r=z-16 -> relT.
__global__ void __launch_bounds__(256, 2) scorerel_kernel(
    const float* __restrict__ Q, const float* __restrict__ K,
    const float* __restrict__ QR, const float* __restrict__ KR,
    float* __restrict__ attn, float* __restrict__ relT)
{
    int z = blockIdx.z;
    int m0 = blockIdx.y * 128, n0 = blockIdx.x * 64;
    bool is_sc = (z < 16);
    if (is_sc && n0 >= m0 + 128) return;

    const float* A = is_sc ? (Q + z * HD) : (QR + (z - 16) * HD);
    const float* B = is_sc ? (K + (z >> 2) * HD) : (KR + (z - 16) * HD);
    int ldb = is_sc ? 256 : 1024;
    float* C = is_sc ? (attn + (size_t)z * L * L) : (relT + (size_t)(z - 16) * L * L);

    float c[2][4][4];
    #pragma unroll
    for (int i = 0; i < 2; i++)
        #pragma unroll
        for (int j = 0; j < 4; j++)
            #pragma unroll
            for (int k = 0; k < 4; k++) c[i][j][k] = 0.f;

    mma3x_compute<1>(A, 1024, B, ldb, m0, n0, 64, c);

    int lane = threadIdx.x & 31, warp = threadIdx.x >> 5;
    int tq = lane >> 2, tr = lane & 3;
    int mb = (warp & 3) * 32, nb = (warp >> 2) * 32;
    #pragma unroll
    for (int ma = 0; ma < 2; ma++) {
        int row = m0 + mb + ma * 16 + tq;
        #pragma unroll
        for (int na = 0; na < 4; na++) {
            int col = n0 + nb + na * 8 + 2 * tr;
            *reinterpret_cast<float2*>(&C[(size_t)row * L + col]) =
                make_float2(c[ma][na][0] * 0.125f, c[ma][na][1] * 0.125f);
            *reinterpret_cast<float2*>(&C[(size_t)(row + 8) * L + col]) =
                make_float2(c[ma][na][2] * 0.125f, c[ma][na][3] * 0.125f);
        }
    }
}

// ---------------- attended (3xTF32 attn@sv + S@wr) ---------------------------
__global__ void __launch_bounds__(256, 2) attended3x_kernel(
    const float* __restrict__ attn, const float* __restrict__ SV,
    const float* __restrict__ S, const float* __restrict__ wr,
    float* __restrict__ ctx)
{
    int h = blockIdx.y;
    int m0 = blockIdx.x * 128;
    int jmax = m0 + 128;

    float c[2][4][4];
    #pragma unroll
    for (int i = 0; i < 2; i++)
        #pragma unroll
        for (int j = 0; j < 4; j++)
            #pragma unroll
            for (int k = 0; k < 4; k++) c[i][j][k] = 0.f;

    mma3x_compute<0>(attn + (size_t)h * L * L, L, SV + (h >> 2) * HD, 256, m0, 0, jmax, c);

    __shared__ float wrs[16][64];
    __shared__ float Ss[128][17];
    int tid = threadIdx.x;
    for (int t = tid; t < 16 * 64; t += 256) {
        int rr = t >> 6, n = t & 63;
        wrs[rr][n] = wr[(size_t)rr * (NH * HD) + h * HD + n];
    }
    for (int t = tid; t < 128 * 16; t += 256) {
        int m = t >> 4, rr = t & 15;
        Ss[m][rr] = S[((size_t)(m0 + m) * NH + h) * NR + rr];
    }
    __syncthreads();

    int lane = tid & 31, warp = tid >> 5;
    int tq = lane >> 2, tr = lane & 3;
    int mb = (warp & 3) * 32, nb = (warp >> 2) * 32;
    #pragma unroll
    for (int rr = 0; rr < 16; rr++) {
        #pragma unroll
        for (int ma = 0; ma < 2; ma++) {
            float s0 = Ss[mb + ma * 16 + tq][rr];
            float s1 = Ss[mb + ma * 16 + tq + 8][rr];
            #pragma unroll
            for (int na = 0; na < 4; na++) {
                int col = nb + na * 8 + 2 * tr;
                float w0 = wrs[rr][col], w1 = wrs[rr][col + 1];
                c[ma][na][0] += s0 * w0; c[ma][na][1] += s0 * w1;
                c[ma][na][2] += s1 * w0; c[ma][na][3] += s1 * w1;
            }
        }
    }
    #pragma unroll
    for (int ma = 0; ma < 2; ma++) {
        int row = m0 + mb + ma * 16 + tq;
        #pragma unroll
        for (int na = 0; na < 4; na++) {
            int col = h * HD + nb + na * 8 + 2 * tr;
            *reinterpret_cast<float2*>(&ctx[(size_t)row * (NH * HD) + col]) =
                make_float2(c[ma][na][0], c[ma][na][1]);
            *reinterpret_cast<float2*>(&ctx[(size_t)(row + 8) * (NH * HD) + col]) =
                make_float2(c[ma][na][2], c[ma][na][3]);
        }
    }
}

// ---------------- causal softmax ---------------------------------------------
__global__ void __launch_bounds__(128) softmax_kernel(float* __restrict__ attn) {
    int row = blockIdx.x;
    int i = row & (L - 1);
    int len = i + 1;
    float4* p4 = reinterpret_cast<float4*>(attn + (size_t)row * L);
    int tid = threadIdx.x;
    int lane = tid & 31, wid = tid >> 5;
    int base = tid * 4;

    float4 v = p4[tid];
    float e0 = (base + 0 < len) ? v.x : -3.0e38f;
    float e1 = (base + 1 < len) ? v.y : -3.0e38f;
    float e2 = (base + 2 < len) ? v.z : -3.0e38f;
    float e3 = (base + 3 < len) ? v.w : -3.0e38f;

    float m = fmaxf(fmaxf(e0, e1), fmaxf(e2, e3));
    #pragma unroll
    for (int off = 16; off > 0; off >>= 1)
        m = fmaxf(m, __shfl_xor_sync(0xFFFFFFFFu, m, off));

    __shared__ float sm[8];
    if (lane == 0) sm[wid] = m;
    __syncthreads();
    m = fmaxf(fmaxf(sm[0], sm[1]), fmaxf(sm[2], sm[3]));

    float x0 = (base + 0 < len) ? __expf(e0 - m) : 0.f;
    float x1 = (base + 1 < len) ? __expf(e1 - m) : 0.f;
    float x2 = (base + 2 < len) ? __expf(e2 - m) : 0.f;
    float x3 = (base + 3 < len) ? __expf(e3 - m) : 0.f;

    float s = x0 + x1 + x2 + x3;
    #pragma unroll
    for (int off = 16; off > 0; off >>= 1)
        s += __shfl_xor_sync(0xFFFFFFFFu, s, off);
    if (lane == 0) sm[4 + wid] = s;
    __syncthreads();
    float inv = 1.f / (sm[4] + sm[5] + sm[6] + sm[7]);

    p4[tid] = make_float4(x0 * inv, x1 * inv, x2 * inv, x3 * inv);
}

// ---- fused: rel[i][j][r] transpose-write + S[i,h,r] accumulation ------------
__global__ void __launch_bounds__(256) s_trans_kernel(
    const float* __restrict__ attn, const float* __restrict__ relT,
    float* __restrict__ rel, float* __restrict__ S)
{
    int i = blockIdx.x;
    int tid = threadIdx.x;
    int h = tid >> 4, r = tid & 15;
    __shared__ float attnS[16][132];
    __shared__ float relS[16][132];
    float acc = 0.f;
    for (int j0 = 0; j0 < L; j0 += 128) {
        #pragma unroll
        for (int e = tid; e < 512; e += 256) {
            int hh = e >> 5, q = e & 31;
            *reinterpret_cast<float4*>(&attnS[hh][q * 4]) =
                *reinterpret_cast<const float4*>(&attn[((size_t)hh * L + i) * L + j0 + q * 4]);
        }
        #pragma unroll
        for (int e = tid; e < 512; e += 256) {
            int rr = e >> 5, q = e & 31;
            *reinterpret_cast<float4*>(&relS[rr][q * 4]) =
                *reinterpret_cast<const float4*>(&relT[((size_t)rr * L + i) * L + j0 + q * 4]);
        }
        __syncthreads();
        // transposed write of the rel output (both sides coalesced)
        #pragma unroll
        for (int e = tid; e < 512; e += 256) {
            int j = e >> 2, rq = e & 3;
            float4 v = make_float4(relS[rq * 4 + 0][j], relS[rq * 4 + 1][j],
                                   relS[rq * 4 + 2][j], relS[rq * 4 + 3][j]);
            *reinterpret_cast<float4*>(&rel[((size_t)i * L + j0 + j) * NR + rq * 4]) = v;
        }
        // S accumulation (attn rows zero beyond diagonal -> unconditional)
        #pragma unroll 16
        for (int jj = 0; jj < 128; jj++)
            acc += attnS[h][jj] * relS[r][jj];
        __syncthreads();
    }
    S[((size_t)i * NH + h) * NR + r] = acc;
}

// ---------------------------------------------------------------------------
extern "C" void kernel_launch(void* const* d_in, const int* in_sizes, int n_in,
                              void* d_out, int out_size) {
    const float* x       = (const float*)d_in[0];
    const float* symbols = (const float*)d_in[1];
    const float* fcos    = (const float*)d_in[2];
    const float* fsin    = (const float*)d_in[3];
    const float* wq_attn = (const float*)d_in[4];
    const float* wk_attn = (const float*)d_in[5];
    const float* wq_rel  = (const float*)d_in[6];
    const float* wk_rel  = (const float*)d_in[7];
    const float* wr      = (const float*)d_in[8];
    const float* wv      = (const float*)d_in[9];
    const float* wo      = (const float*)d_in[10];

    float* out  = (float*)d_out;
    float* attn = out + (size_t)L * NH * HD;
    float* rel  = attn + (size_t)NH * L * L;

    float *Q, *K, *QR, *KR, *SV, *S, *CTX, *RELT;
    cudaGetSymbolAddress((void**)&Q,  g_Q);
    cudaGetSymbolAddress((void**)&K,  g_K);
    cudaGetSymbolAddress((void**)&QR, g_QR);
    cudaGetSymbolAddress((void**)&KR, g_KR);
    cudaGetSymbolAddress((void**)&SV, g_SV);
    cudaGetSymbolAddress((void**)&S,  g_S);
    cudaGetSymbolAddress((void**)&CTX, g_CTX);
    cudaGetSymbolAddress((void**)&RELT, g_RELT);

    // 1) projections + fused RoPE
    proj_mma_kernel<<<dim3(4, 56), 256>>>(x, symbols, wq_attn, wq_rel, wk_rel,
                                          wk_attn, wv, fcos, fsin, Q, K, QR, KR, SV);

    // 2) fused scores + relations (3xTF32)
    scorerel_kernel<<<dim3(8, 4, 32), 256>>>(Q, K, QR, KR, attn, RELT);

    // 3) softmax
    softmax_kernel<<<NH * L, 128>>>(attn);

    // 4) fused rel transpose-out + S factorization
    s_trans_kernel<<<L, 256>>>(attn, RELT, rel, S);

    // 5) ctx = attn@sv (3xTF32) + S@wr
    attended3x_kernel<<<dim3(4, NH), 256>>>(attn, SV, S, wr, CTX);

    // 6) out = ctx @ wo
    out_mma_kernel<<<dim3(4, 16), 256>>>(CTX, wo, out);
}